// round 1
// baseline (speedup 1.0000x reference)
#include <cuda_runtime.h>
#include <math.h>

#define T_STEPS 256
#define B_DIM   128
#define H_DIM   2048

// Scratch: xproj for all timesteps (256 MB) + double-buffered hidden state.
__device__ float g_xproj[(size_t)T_STEPS * B_DIM * H_DIM];
__device__ float g_h[2][B_DIM * H_DIM];

// ---------------------------------------------------------------------------
// Zero-init h0 (graph-safe; no cudaMemsetAsync dependence on capture stream)
// ---------------------------------------------------------------------------
__global__ void zero_h0_kernel() {
    int i = blockIdx.x * blockDim.x + threadIdx.x;
    if (i < B_DIM * H_DIM) g_h[0][i] = 0.0f;
}

// ---------------------------------------------------------------------------
// Kernel 1: xproj = X @ W_in + bias
// X: (M=32768, K=2048) row-major, W_in: (K=2048, N=2048) row-major
// Classic 128x128x16 SGEMM, 256 threads, 8x8 per thread, float4 loads.
// ---------------------------------------------------------------------------
__global__ __launch_bounds__(256) void gemm_xproj_kernel(
    const float* __restrict__ A, const float* __restrict__ Bm,
    const float* __restrict__ bias)
{
    const int N = H_DIM, K = H_DIM;
    __shared__ float As[16][128];
    __shared__ float Bs[16][128];

    const int tid = threadIdx.x;
    const int cCol = blockIdx.x;   // N tile (0..15)
    const int cRow = blockIdx.y;   // M tile (0..255)

    const float* Ablk = A + (size_t)cRow * 128 * K;
    const float* Bblk = Bm + cCol * 128;
    float* Cout = g_xproj + (size_t)cRow * 128 * N + cCol * 128;

    float acc[8][8] = {};

    const int innerRowA = tid / 4;   // 0..63, 2 passes (stride 64)
    const int innerColA = tid % 4;   // float4 index in K (0..3 -> cols 0..15)
    const int innerRowB = tid / 32;  // 0..7, 2 passes (stride 8)
    const int innerColB = tid % 32;  // float4 index in N

    const int tr = tid / 16;         // 0..15
    const int tc = tid % 16;         // 0..15

    for (int k0 = 0; k0 < K; k0 += 16) {
        #pragma unroll
        for (int p = 0; p < 2; p++) {
            float4 a = *(const float4*)(Ablk + (size_t)(innerRowA + p * 64) * K
                                        + k0 + innerColA * 4);
            As[innerColA * 4 + 0][innerRowA + p * 64] = a.x;
            As[innerColA * 4 + 1][innerRowA + p * 64] = a.y;
            As[innerColA * 4 + 2][innerRowA + p * 64] = a.z;
            As[innerColA * 4 + 3][innerRowA + p * 64] = a.w;
        }
        #pragma unroll
        for (int p = 0; p < 2; p++) {
            float4 b = *(const float4*)(Bblk + (size_t)(k0 + innerRowB + p * 8) * N
                                        + innerColB * 4);
            *(float4*)&Bs[innerRowB + p * 8][innerColB * 4] = b;
        }
        __syncthreads();

        #pragma unroll
        for (int kk = 0; kk < 16; kk++) {
            float ra[8], rb[8];
            #pragma unroll
            for (int i = 0; i < 8; i++) ra[i] = As[kk][tr * 8 + i];
            #pragma unroll
            for (int j = 0; j < 8; j++) rb[j] = Bs[kk][tc * 8 + j];
            #pragma unroll
            for (int i = 0; i < 8; i++)
                #pragma unroll
                for (int j = 0; j < 8; j++)
                    acc[i][j] += ra[i] * rb[j];
        }
        __syncthreads();
    }

    #pragma unroll
    for (int i = 0; i < 8; i++) {
        #pragma unroll
        for (int j = 0; j < 8; j++) {
            int n = cCol * 128 + tc * 8 + j;
            Cout[(size_t)(tr * 8 + i) * N + tc * 8 + j] = acc[i][j] + bias[n];
        }
    }
}

// ---------------------------------------------------------------------------
// Kernel 2 (x256): h_next = tanh(xproj_t + h_prev @ W_rec)
// M=128, N=2048, K=2048. Tiles 32x64x16, 128 threads, 4x4 per thread.
// Grid = (32, 4) = 128 CTAs (w_rec stays resident in L2 across steps).
// Double-buffered h in g_h; final step writes d_out.
// ---------------------------------------------------------------------------
__global__ __launch_bounds__(128) void step_kernel(
    const float* __restrict__ W, float* __restrict__ final_out, int t)
{
    const int N = H_DIM, K = H_DIM;
    __shared__ float As[16][32];
    __shared__ float Bs[16][64];

    const float* __restrict__ xp    = g_xproj + (size_t)t * B_DIM * H_DIM;
    const float* __restrict__ hprev = g_h[t & 1];
    float* __restrict__ hout = (t == T_STEPS - 1) ? final_out : g_h[(t + 1) & 1];

    const int tid  = threadIdx.x;
    const int cCol = blockIdx.x;   // N tile (0..31)
    const int cRow = blockIdx.y;   // M tile (0..3)

    const float* Ablk = hprev + (size_t)cRow * 32 * K;
    const float* Bblk = W + cCol * 64;

    float acc[4][4] = {};

    const int innerRowA = tid / 4;   // 0..31 (covers all 32 rows, 1 pass)
    const int innerColA = tid % 4;   // float4 index (cols 0..15)
    const int innerRowB = tid / 16;  // 0..7, 2 passes (stride 8)
    const int innerColB = tid % 16;  // float4 index in N (cols 0..63)

    const int tr = tid / 16;         // 0..7
    const int tc = tid % 16;         // 0..15

    for (int k0 = 0; k0 < K; k0 += 16) {
        float4 a = *(const float4*)(Ablk + (size_t)innerRowA * K + k0 + innerColA * 4);
        As[innerColA * 4 + 0][innerRowA] = a.x;
        As[innerColA * 4 + 1][innerRowA] = a.y;
        As[innerColA * 4 + 2][innerRowA] = a.z;
        As[innerColA * 4 + 3][innerRowA] = a.w;

        #pragma unroll
        for (int p = 0; p < 2; p++) {
            float4 b = *(const float4*)(Bblk + (size_t)(k0 + innerRowB + p * 8) * N
                                        + innerColB * 4);
            *(float4*)&Bs[innerRowB + p * 8][innerColB * 4] = b;
        }
        __syncthreads();

        #pragma unroll
        for (int kk = 0; kk < 16; kk++) {
            float ra[4], rb[4];
            #pragma unroll
            for (int i = 0; i < 4; i++) ra[i] = As[kk][tr * 4 + i];
            #pragma unroll
            for (int j = 0; j < 4; j++) rb[j] = Bs[kk][tc * 4 + j];
            #pragma unroll
            for (int i = 0; i < 4; i++)
                #pragma unroll
                for (int j = 0; j < 4; j++)
                    acc[i][j] += ra[i] * rb[j];
        }
        __syncthreads();
    }

    #pragma unroll
    for (int i = 0; i < 4; i++) {
        #pragma unroll
        for (int j = 0; j < 4; j++) {
            size_t m = (size_t)cRow * 32 + tr * 4 + i;
            size_t n = (size_t)cCol * 64 + tc * 4 + j;
            hout[m * N + n] = tanhf(acc[i][j] + xp[m * N + n]);
        }
    }
}

// ---------------------------------------------------------------------------
// Launch: all work enqueued on the capture stream. No allocs, no syncs.
// Inputs (metadata order): x, w_in, w_rec, bias. Output: h_final (128, 2048).
// ---------------------------------------------------------------------------
extern "C" void kernel_launch(void* const* d_in, const int* in_sizes, int n_in,
                              void* d_out, int out_size)
{
    const float* x     = (const float*)d_in[0];
    const float* w_in  = (const float*)d_in[1];
    const float* w_rec = (const float*)d_in[2];
    const float* bias  = (const float*)d_in[3];
    float* out = (float*)d_out;

    // h0 = 0
    zero_h0_kernel<<<(B_DIM * H_DIM + 255) / 256, 256>>>();

    // xproj = x @ w_in + bias
    dim3 g1(H_DIM / 128, (T_STEPS * B_DIM) / 128);  // (16, 256)
    gemm_xproj_kernel<<<g1, 256>>>(x, w_in, bias);

    // Sequential scan
    dim3 g2(H_DIM / 64, B_DIM / 32);  // (32, 4) = 128 CTAs
    for (int t = 0; t < T_STEPS; t++) {
        step_kernel<<<g2, 128>>>(w_rec, out, t);
    }
}

// round 3
// speedup vs baseline: 3.2949x; 3.2949x over previous
#include <cuda_runtime.h>
#include <cuda_bf16.h>
#include <math.h>
#include <stdint.h>

#define T_STEPS 256
#define B_DIM   128
#define H_DIM   2048
#define KC      64                 // K elems per pipeline chunk
#define NCH     (H_DIM / KC)       // 32
#define ROWB    144                // padded smem row bytes (72 bf16): +4 banks/row

// ---- step kernel smem layout (stage = 27648 B, 2 stages = 55296) ----
#define S_AH 0
#define S_AL 9216
#define S_BH 18432
#define S_BL 23040
#define S_STG 27648

// ---- xproj kernel smem layout (stage = 55296 B, 2 stages = 110592) ----
#define X_AH 0
#define X_AL 18432
#define X_BH 36864
#define X_BL 46080
#define X_STG 55296

// ---------------------------------------------------------------------------
// Device scratch (no allocations allowed anywhere)
// ---------------------------------------------------------------------------
__device__ __align__(128) float g_xproj[(size_t)T_STEPS * B_DIM * H_DIM];   // 256 MB
__device__ __align__(128) __nv_bfloat16 g_h_hi[2][B_DIM * H_DIM];
__device__ __align__(128) __nv_bfloat16 g_h_lo[2][B_DIM * H_DIM];
__device__ __align__(128) __nv_bfloat16 g_wr_hi[(size_t)H_DIM * H_DIM];     // w_rec^T splits
__device__ __align__(128) __nv_bfloat16 g_wr_lo[(size_t)H_DIM * H_DIM];
__device__ __align__(128) __nv_bfloat16 g_wi_hi[(size_t)H_DIM * H_DIM];     // w_in^T splits
__device__ __align__(128) __nv_bfloat16 g_wi_lo[(size_t)H_DIM * H_DIM];
__device__ __align__(128) __nv_bfloat16 g_x_hi[(size_t)T_STEPS * B_DIM * H_DIM];
__device__ __align__(128) __nv_bfloat16 g_x_lo[(size_t)T_STEPS * B_DIM * H_DIM];

// ---------------------------------------------------------------------------
// PTX helpers — everything here is legal on plain sm_103 target
// ---------------------------------------------------------------------------
__device__ __forceinline__ uint32_t smem_u32(const void* p) {
    uint32_t a;
    asm("{ .reg .u64 t; cvta.to.shared.u64 t, %1; cvt.u32.u64 %0, t; }"
        : "=r"(a) : "l"(p));
    return a;
}
__device__ __forceinline__ void cp16(uint32_t dst, const void* src) {
    asm volatile("cp.async.cg.shared.global [%0], [%1], 16;"
                 :: "r"(dst), "l"(src) : "memory");
}
__device__ __forceinline__ void cp_commit() {
    asm volatile("cp.async.commit_group;" ::: "memory");
}
__device__ __forceinline__ void cp_wait1() {
    asm volatile("cp.async.wait_group 1;" ::: "memory");
}
__device__ __forceinline__ void cp_wait0() {
    asm volatile("cp.async.wait_group 0;" ::: "memory");
}
__device__ __forceinline__ void ldsm4(uint32_t addr, uint32_t r[4]) {
    asm volatile("ldmatrix.sync.aligned.m8n8.x4.shared.b16 {%0,%1,%2,%3}, [%4];"
                 : "=r"(r[0]), "=r"(r[1]), "=r"(r[2]), "=r"(r[3]) : "r"(addr));
}
__device__ __forceinline__ void mma16816(float c[4], const uint32_t a[4],
                                         uint32_t b0, uint32_t b1) {
    asm volatile("mma.sync.aligned.m16n8k16.row.col.f32.bf16.bf16.f32 "
                 "{%0,%1,%2,%3},{%4,%5,%6,%7},{%8,%9},{%0,%1,%2,%3};"
                 : "+f"(c[0]), "+f"(c[1]), "+f"(c[2]), "+f"(c[3])
                 : "r"(a[0]), "r"(a[1]), "r"(a[2]), "r"(a[3]), "r"(b0), "r"(b1));
}

// ---------------------------------------------------------------------------
// FMA-only accurate tanh (avoid MUFU throughput cliff), |err| ~2e-7
// ---------------------------------------------------------------------------
__device__ __forceinline__ float fast_tanh(float x) {
    float ax = fminf(fabsf(x), 9.0f);
    float t  = ax * 2.8853900817779268f;           // 2*log2(e)*|x|
    float f  = t + 12582912.0f;
    int   n  = __float_as_int(f) - 0x4B400000;
    float r  = t - (f - 12582912.0f);
    float p = 1.5403530e-4f;
    p = fmaf(p, r, 1.3333558e-3f);
    p = fmaf(p, r, 9.6181291e-3f);
    p = fmaf(p, r, 5.5504109e-2f);
    p = fmaf(p, r, 2.4022651e-1f);
    p = fmaf(p, r, 6.9314718e-1f);
    p = fmaf(p, r, 1.0f);
    float e2x = p * __int_as_float((n + 127) << 23);
    float d = e2x + 1.0f;
    float rc = __int_as_float(0x7EF311C3 - __float_as_int(d));
    rc = rc * fmaf(-d, rc, 2.0f);
    rc = rc * fmaf(-d, rc, 2.0f);
    rc = rc * fmaf(-d, rc, 2.0f);
    float y = fmaf(-2.0f, rc, 1.0f);
    return __int_as_float(__float_as_int(y) | (__float_as_int(x) & 0x80000000));
}

// ---------------------------------------------------------------------------
// Prep kernels
// ---------------------------------------------------------------------------
__global__ void init_h0_kernel() {
    int i = blockIdx.x * blockDim.x + threadIdx.x;
    if (i < B_DIM * H_DIM) {
        g_h_hi[0][i] = __float2bfloat16(0.0f);
        g_h_lo[0][i] = __float2bfloat16(0.0f);
    }
}

// x (fp32) -> hi/lo bf16 splits, 4 elems per thread
__global__ __launch_bounds__(256) void split_x_kernel(const float* __restrict__ x) {
    size_t i = ((size_t)blockIdx.x * blockDim.x + threadIdx.x) * 4;
    float4 v = *(const float4*)(x + i);
    __nv_bfloat16 h0 = __float2bfloat16(v.x), h1 = __float2bfloat16(v.y);
    __nv_bfloat16 h2 = __float2bfloat16(v.z), h3 = __float2bfloat16(v.w);
    *(__nv_bfloat162*)(g_x_hi + i)     = __nv_bfloat162{h0, h1};
    *(__nv_bfloat162*)(g_x_hi + i + 2) = __nv_bfloat162{h2, h3};
    *(__nv_bfloat162*)(g_x_lo + i) = __nv_bfloat162{
        __float2bfloat16(v.x - __bfloat162float(h0)),
        __float2bfloat16(v.y - __bfloat162float(h1))};
    *(__nv_bfloat162*)(g_x_lo + i + 2) = __nv_bfloat162{
        __float2bfloat16(v.z - __bfloat162float(h2)),
        __float2bfloat16(v.w - __bfloat162float(h3))};
}

// W (k,n) fp32 -> W^T (n,k) hi/lo bf16 splits. 32x32 tiles.
__global__ __launch_bounds__(256) void wsplit_kernel(
    const float* __restrict__ W, __nv_bfloat16* __restrict__ dh,
    __nv_bfloat16* __restrict__ dl)
{
    __shared__ float tile[32][33];
    int tx = threadIdx.x, ty = threadIdx.y;
    int k0 = blockIdx.y * 32;
    int n0 = blockIdx.x * 32;
    #pragma unroll
    for (int j = 0; j < 32; j += 8)
        tile[ty + j][tx] = W[(size_t)(k0 + ty + j) * H_DIM + n0 + tx];
    __syncthreads();
    #pragma unroll
    for (int j = 0; j < 32; j += 8) {
        float v = tile[tx][ty + j];
        __nv_bfloat16 hi = __float2bfloat16(v);
        __nv_bfloat16 lo = __float2bfloat16(v - __bfloat162float(hi));
        size_t idx = (size_t)(n0 + ty + j) * H_DIM + k0 + tx;
        dh[idx] = hi;
        dl[idx] = lo;
    }
}

// ---------------------------------------------------------------------------
// xproj = X @ W_in + bias  (split-bf16 HMMA, 3 products, fp32 out)
// CTA tile 128x64, 8 warps (4x2), warp tile 32x32. Grid (32, 256).
// ---------------------------------------------------------------------------
__global__ __launch_bounds__(256) void xproj_mma_kernel(const float* __restrict__ bias) {
    extern __shared__ char smem[];
    const uint32_t sb = smem_u32(smem);
    const int tid = threadIdx.x, wid = tid >> 5, lane = tid & 31;
    const int m0 = blockIdx.y * 128;
    const int n0 = blockIdx.x * 64;

    const __nv_bfloat16* __restrict__ Ah = g_x_hi;
    const __nv_bfloat16* __restrict__ Al = g_x_lo;
    const __nv_bfloat16* __restrict__ Bh = g_wi_hi + (size_t)n0 * H_DIM;
    const __nv_bfloat16* __restrict__ Bl = g_wi_lo + (size_t)n0 * H_DIM;

    float c[2][4][4];
    #pragma unroll
    for (int i = 0; i < 2; i++)
        #pragma unroll
        for (int j = 0; j < 4; j++)
            #pragma unroll
            for (int q = 0; q < 4; q++) c[i][j][q] = 0.0f;

    auto load_stage = [&](int s, int cch) {
        const int k0 = cch * KC;
        uint32_t base = sb + s * X_STG;
        #pragma unroll
        for (int j = 0; j < 4; j++) {            // A: 128 rows x 8 chunks
            int idx = tid + j * 256;
            int r = idx >> 3, kc = idx & 7;
            size_t go = (size_t)(m0 + r) * H_DIM + k0 + kc * 8;
            cp16(base + X_AH + r * ROWB + kc * 16, Ah + go);
            cp16(base + X_AL + r * ROWB + kc * 16, Al + go);
        }
        #pragma unroll
        for (int j = 0; j < 2; j++) {            // B: 64 rows x 8 chunks
            int idx = tid + j * 256;
            int r = idx >> 3, kc = idx & 7;
            size_t go = (size_t)r * H_DIM + k0 + kc * 8;
            cp16(base + X_BH + r * ROWB + kc * 16, Bh + go);
            cp16(base + X_BL + r * ROWB + kc * 16, Bl + go);
        }
        cp_commit();
    };

    const int mwb = (wid >> 1) * 32;
    const int nwb = (wid & 1) * 32;
    const uint32_t aOff = (uint32_t)((lane & 15) * ROWB + ((lane >> 4) * 8) * 2);
    const uint32_t bOff = (uint32_t)(((lane & 7) | ((lane >> 1) & 8)) * ROWB + (lane & 8) * 2);

    auto compute_stage = [&](int s) {
        uint32_t base = sb + s * X_STG;
        uint32_t aH = base + X_AH + mwb * ROWB + aOff;
        uint32_t aL = base + X_AL + mwb * ROWB + aOff;
        uint32_t bH = base + X_BH + nwb * ROWB + bOff;
        uint32_t bL = base + X_BL + nwb * ROWB + bOff;
        #pragma unroll
        for (int kk = 0; kk < KC / 16; kk++) {
            uint32_t ah[2][4], al[2][4], bh[8], bl[8];
            ldsm4(aH + kk * 32, ah[0]);
            ldsm4(aH + 16 * ROWB + kk * 32, ah[1]);
            ldsm4(aL + kk * 32, al[0]);
            ldsm4(aL + 16 * ROWB + kk * 32, al[1]);
            ldsm4(bH + kk * 32, bh);
            ldsm4(bH + 16 * ROWB + kk * 32, bh + 4);
            ldsm4(bL + kk * 32, bl);
            ldsm4(bL + 16 * ROWB + kk * 32, bl + 4);
            #pragma unroll
            for (int mi = 0; mi < 2; mi++)
                #pragma unroll
                for (int ni = 0; ni < 4; ni++) {
                    mma16816(c[mi][ni], ah[mi], bh[2 * ni], bh[2 * ni + 1]);
                    mma16816(c[mi][ni], ah[mi], bl[2 * ni], bl[2 * ni + 1]);
                    mma16816(c[mi][ni], al[mi], bh[2 * ni], bh[2 * ni + 1]);
                }
        }
    };

    load_stage(0, 0);
    #pragma unroll 1
    for (int cch = 0; cch < NCH; cch++) {
        if (cch + 1 < NCH) { load_stage((cch + 1) & 1, cch + 1); cp_wait1(); }
        else cp_wait0();
        __syncthreads();
        compute_stage(cch & 1);
        __syncthreads();
    }

    // epilogue: + bias, fp32 store
    #pragma unroll
    for (int mi = 0; mi < 2; mi++)
        #pragma unroll
        for (int ni = 0; ni < 4; ni++) {
            int r  = m0 + mwb + mi * 16 + (lane >> 2);
            int cc = n0 + nwb + ni * 8 + 2 * (lane & 3);
            float bx = bias[cc], by = bias[cc + 1];
            size_t o0 = (size_t)r * H_DIM + cc;
            size_t o1 = o0 + (size_t)8 * H_DIM;
            *(float2*)(g_xproj + o0) = make_float2(c[mi][ni][0] + bx, c[mi][ni][1] + by);
            *(float2*)(g_xproj + o1) = make_float2(c[mi][ni][2] + bx, c[mi][ni][3] + by);
        }
}

// ---------------------------------------------------------------------------
// Step kernel (x256): h_next = tanh(xproj_t + h @ w_rec), split-bf16 HMMA.
// CTA tile 64x32, 4 warps (2x2), warp tile 32x16. Grid (64, 2) = 128 CTAs.
// ---------------------------------------------------------------------------
__global__ __launch_bounds__(128) void step_mma_kernel(float* __restrict__ final_out, int t) {
    extern __shared__ char smem[];
    const uint32_t sb = smem_u32(smem);
    const int tid = threadIdx.x, wid = tid >> 5, lane = tid & 31;
    const int m0 = blockIdx.y * 64;
    const int n0 = blockIdx.x * 32;

    const __nv_bfloat16* __restrict__ Ah = g_h_hi[t & 1];
    const __nv_bfloat16* __restrict__ Al = g_h_lo[t & 1];
    const __nv_bfloat16* __restrict__ Bh = g_wr_hi + (size_t)n0 * H_DIM;
    const __nv_bfloat16* __restrict__ Bl = g_wr_lo + (size_t)n0 * H_DIM;

    float c[2][2][4];
    #pragma unroll
    for (int i = 0; i < 2; i++)
        #pragma unroll
        for (int j = 0; j < 2; j++)
            #pragma unroll
            for (int q = 0; q < 4; q++) c[i][j][q] = 0.0f;

    auto load_stage = [&](int s, int cch) {
        const int k0 = cch * KC;
        uint32_t base = sb + s * S_STG;
        #pragma unroll
        for (int j = 0; j < 4; j++) {            // A: 64 rows x 8 chunks (x2 splits)
            int idx = tid + j * 128;
            int r = idx >> 3, kc = idx & 7;
            size_t go = (size_t)(m0 + r) * H_DIM + k0 + kc * 8;
            cp16(base + S_AH + r * ROWB + kc * 16, Ah + go);
            cp16(base + S_AL + r * ROWB + kc * 16, Al + go);
        }
        #pragma unroll
        for (int j = 0; j < 2; j++) {            // B: 32 rows x 8 chunks (x2 splits)
            int idx = tid + j * 128;
            int r = idx >> 3, kc = idx & 7;
            size_t go = (size_t)r * H_DIM + k0 + kc * 8;
            cp16(base + S_BH + r * ROWB + kc * 16, Bh + go);
            cp16(base + S_BL + r * ROWB + kc * 16, Bl + go);
        }
        cp_commit();
    };

    const int mwb = (wid >> 1) * 32;
    const int nwb = (wid & 1) * 16;
    const uint32_t aOff = (uint32_t)((lane & 15) * ROWB + ((lane >> 4) * 8) * 2);
    const uint32_t bOff = (uint32_t)(((lane & 7) | ((lane >> 1) & 8)) * ROWB + (lane & 8) * 2);

    auto compute_stage = [&](int s) {
        uint32_t base = sb + s * S_STG;
        uint32_t aH = base + S_AH + mwb * ROWB + aOff;
        uint32_t aL = base + S_AL + mwb * ROWB + aOff;
        uint32_t bH = base + S_BH + nwb * ROWB + bOff;
        uint32_t bL = base + S_BL + nwb * ROWB + bOff;
        #pragma unroll
        for (int kk = 0; kk < KC / 16; kk++) {
            uint32_t ah[2][4], al[2][4], bh[4], bl[4];
            ldsm4(aH + kk * 32, ah[0]);
            ldsm4(aH + 16 * ROWB + kk * 32, ah[1]);
            ldsm4(aL + kk * 32, al[0]);
            ldsm4(aL + 16 * ROWB + kk * 32, al[1]);
            ldsm4(bH + kk * 32, bh);
            ldsm4(bL + kk * 32, bl);
            #pragma unroll
            for (int mi = 0; mi < 2; mi++)
                #pragma unroll
                for (int ni = 0; ni < 2; ni++) {
                    mma16816(c[mi][ni], ah[mi], bh[2 * ni], bh[2 * ni + 1]);
                    mma16816(c[mi][ni], ah[mi], bl[2 * ni], bl[2 * ni + 1]);
                    mma16816(c[mi][ni], al[mi], bh[2 * ni], bh[2 * ni + 1]);
                }
        }
    };

    load_stage(0, 0);
    #pragma unroll 1
    for (int cch = 0; cch < NCH; cch++) {
        if (cch + 1 < NCH) { load_stage((cch + 1) & 1, cch + 1); cp_wait1(); }
        else cp_wait0();
        __syncthreads();
        compute_stage(cch & 1);
        __syncthreads();
    }

    // epilogue: tanh(acc + xproj_t), write h splits (or final fp32)
    const float* __restrict__ xp = g_xproj + (size_t)t * B_DIM * H_DIM;
    const bool last = (t == T_STEPS - 1);
    __nv_bfloat16* __restrict__ Hh = g_h_hi[(t + 1) & 1];
    __nv_bfloat16* __restrict__ Hl = g_h_lo[(t + 1) & 1];

    #pragma unroll
    for (int mi = 0; mi < 2; mi++)
        #pragma unroll
        for (int ni = 0; ni < 2; ni++) {
            int r  = m0 + mwb + mi * 16 + (lane >> 2);
            int cc = n0 + nwb + ni * 8 + 2 * (lane & 3);
            size_t o0 = (size_t)r * H_DIM + cc;
            size_t o1 = o0 + (size_t)8 * H_DIM;
            float2 x0 = *(const float2*)(xp + o0);
            float2 x1 = *(const float2*)(xp + o1);
            float v00 = fast_tanh(c[mi][ni][0] + x0.x);
            float v01 = fast_tanh(c[mi][ni][1] + x0.y);
            float v10 = fast_tanh(c[mi][ni][2] + x1.x);
            float v11 = fast_tanh(c[mi][ni][3] + x1.y);
            if (last) {
                *(float2*)(final_out + o0) = make_float2(v00, v01);
                *(float2*)(final_out + o1) = make_float2(v10, v11);
            } else {
                __nv_bfloat16 h00 = __float2bfloat16(v00), h01 = __float2bfloat16(v01);
                __nv_bfloat16 h10 = __float2bfloat16(v10), h11 = __float2bfloat16(v11);
                *(__nv_bfloat162*)(Hh + o0) = __nv_bfloat162{h00, h01};
                *(__nv_bfloat162*)(Hh + o1) = __nv_bfloat162{h10, h11};
                *(__nv_bfloat162*)(Hl + o0) = __nv_bfloat162{
                    __float2bfloat16(v00 - __bfloat162float(h00)),
                    __float2bfloat16(v01 - __bfloat162float(h01))};
                *(__nv_bfloat162*)(Hl + o1) = __nv_bfloat162{
                    __float2bfloat16(v10 - __bfloat162float(h10)),
                    __float2bfloat16(v11 - __bfloat162float(h11))};
            }
        }
}

// ---------------------------------------------------------------------------
// Host launch — plain kernel launches only, graph-capturable
// ---------------------------------------------------------------------------
extern "C" void kernel_launch(void* const* d_in, const int* in_sizes, int n_in,
                              void* d_out, int out_size)
{
    const float* x     = (const float*)d_in[0];
    const float* w_in  = (const float*)d_in[1];
    const float* w_rec = (const float*)d_in[2];
    const float* bias  = (const float*)d_in[3];
    float* out = (float*)d_out;

    void *p_wr_h, *p_wr_l, *p_wi_h, *p_wi_l;
    cudaGetSymbolAddress(&p_wr_h, g_wr_hi);
    cudaGetSymbolAddress(&p_wr_l, g_wr_lo);
    cudaGetSymbolAddress(&p_wi_h, g_wi_hi);
    cudaGetSymbolAddress(&p_wi_l, g_wi_lo);

    cudaFuncSetAttribute(step_mma_kernel,
                         cudaFuncAttributeMaxDynamicSharedMemorySize, 2 * S_STG);
    cudaFuncSetAttribute(xproj_mma_kernel,
                         cudaFuncAttributeMaxDynamicSharedMemorySize, 2 * X_STG);

    // prep
    init_h0_kernel<<<(B_DIM * H_DIM + 255) / 256, 256>>>();
    split_x_kernel<<<(int)(((size_t)T_STEPS * B_DIM * H_DIM) / 4 / 256), 256>>>(x);
    wsplit_kernel<<<dim3(H_DIM / 32, H_DIM / 32), dim3(32, 8)>>>(
        w_rec, (__nv_bfloat16*)p_wr_h, (__nv_bfloat16*)p_wr_l);
    wsplit_kernel<<<dim3(H_DIM / 32, H_DIM / 32), dim3(32, 8)>>>(
        w_in, (__nv_bfloat16*)p_wi_h, (__nv_bfloat16*)p_wi_l);

    // xproj (tensor-core)
    xproj_mma_kernel<<<dim3(H_DIM / 64, (T_STEPS * B_DIM) / 128), 256, 2 * X_STG>>>(bias);

    // sequential scan (tensor-core)
    for (int t = 0; t < T_STEPS; t++) {
        step_mma_kernel<<<dim3(H_DIM / 32, B_DIM / 64), 128, 2 * S_STG>>>(out, t);
    }
}

// round 4
// speedup vs baseline: 3.4076x; 1.0342x over previous
#include <cuda_runtime.h>
#include <cuda_bf16.h>
#include <math.h>
#include <stdint.h>

#define T_STEPS 256
#define B_DIM   128
#define H_DIM   2048
#define KC      64                 // K elems per pipeline chunk
#define NCH     (H_DIM / KC)       // 32
#define ROWB    144                // padded smem row bytes for staged tiles

// ---- persistent scan kernel smem ----
#define WPITCH   4112              // 2048*2 + 16 pad: conflict-free ldsm rows
#define WH_SZ    (32 * WPITCH)     // 131584 B resident W_hi^T slice
#define ST_AH    0
#define ST_AL    9216
#define ST_WL    18432
#define ST_SZ    23040             // AH 9216 + AL 9216 + WL 4608
#define SMEM_SCAN (WH_SZ + 2 * ST_SZ)   // 177664

// ---- xproj kernel smem (stage = 55296 B, 2 stages) ----
#define X_AH 0
#define X_AL 18432
#define X_BH 36864
#define X_BL 46080
#define X_STG 55296

// ---------------------------------------------------------------------------
// Device scratch (no allocations allowed anywhere)
// ---------------------------------------------------------------------------
__device__ __align__(128) float g_xproj[(size_t)T_STEPS * B_DIM * H_DIM];   // 256 MB
__device__ __align__(128) __nv_bfloat16 g_h_hi[2][B_DIM * H_DIM];
__device__ __align__(128) __nv_bfloat16 g_h_lo[2][B_DIM * H_DIM];
__device__ __align__(128) __nv_bfloat16 g_wr_hi[(size_t)H_DIM * H_DIM];     // w_rec^T splits
__device__ __align__(128) __nv_bfloat16 g_wr_lo[(size_t)H_DIM * H_DIM];
__device__ __align__(128) __nv_bfloat16 g_wi_hi[(size_t)H_DIM * H_DIM];     // w_in^T splits
__device__ __align__(128) __nv_bfloat16 g_wi_lo[(size_t)H_DIM * H_DIM];
__device__ __align__(128) __nv_bfloat16 g_x_hi[(size_t)T_STEPS * B_DIM * H_DIM];
__device__ __align__(128) __nv_bfloat16 g_x_lo[(size_t)T_STEPS * B_DIM * H_DIM];
__device__ unsigned g_bar[T_STEPS];                                          // grid barrier counters

// ---------------------------------------------------------------------------
// PTX helpers — legal on plain sm_103 target
// ---------------------------------------------------------------------------
__device__ __forceinline__ uint32_t smem_u32(const void* p) {
    uint32_t a;
    asm("{ .reg .u64 t; cvta.to.shared.u64 t, %1; cvt.u32.u64 %0, t; }"
        : "=r"(a) : "l"(p));
    return a;
}
__device__ __forceinline__ void cp16(uint32_t dst, const void* src) {
    asm volatile("cp.async.cg.shared.global [%0], [%1], 16;"
                 :: "r"(dst), "l"(src) : "memory");
}
__device__ __forceinline__ void cp_commit() {
    asm volatile("cp.async.commit_group;" ::: "memory");
}
__device__ __forceinline__ void cp_wait1() {
    asm volatile("cp.async.wait_group 1;" ::: "memory");
}
__device__ __forceinline__ void cp_wait0() {
    asm volatile("cp.async.wait_group 0;" ::: "memory");
}
__device__ __forceinline__ void ldsm4(uint32_t addr, uint32_t r[4]) {
    asm volatile("ldmatrix.sync.aligned.m8n8.x4.shared.b16 {%0,%1,%2,%3}, [%4];"
                 : "=r"(r[0]), "=r"(r[1]), "=r"(r[2]), "=r"(r[3]) : "r"(addr));
}
__device__ __forceinline__ void mma16816(float c[4], const uint32_t a[4],
                                         uint32_t b0, uint32_t b1) {
    asm volatile("mma.sync.aligned.m16n8k16.row.col.f32.bf16.bf16.f32 "
                 "{%0,%1,%2,%3},{%4,%5,%6,%7},{%8,%9},{%0,%1,%2,%3};"
                 : "+f"(c[0]), "+f"(c[1]), "+f"(c[2]), "+f"(c[3])
                 : "r"(a[0]), "r"(a[1]), "r"(a[2]), "r"(a[3]), "r"(b0), "r"(b1));
}

// ---------------------------------------------------------------------------
// FMA-only accurate tanh, |err| ~2e-7
// ---------------------------------------------------------------------------
__device__ __forceinline__ float fast_tanh(float x) {
    float ax = fminf(fabsf(x), 9.0f);
    float t  = ax * 2.8853900817779268f;
    float f  = t + 12582912.0f;
    int   n  = __float_as_int(f) - 0x4B400000;
    float r  = t - (f - 12582912.0f);
    float p = 1.5403530e-4f;
    p = fmaf(p, r, 1.3333558e-3f);
    p = fmaf(p, r, 9.6181291e-3f);
    p = fmaf(p, r, 5.5504109e-2f);
    p = fmaf(p, r, 2.4022651e-1f);
    p = fmaf(p, r, 6.9314718e-1f);
    p = fmaf(p, r, 1.0f);
    float e2x = p * __int_as_float((n + 127) << 23);
    float d = e2x + 1.0f;
    float rc = __int_as_float(0x7EF311C3 - __float_as_int(d));
    rc = rc * fmaf(-d, rc, 2.0f);
    rc = rc * fmaf(-d, rc, 2.0f);
    rc = rc * fmaf(-d, rc, 2.0f);
    float y = fmaf(-2.0f, rc, 1.0f);
    return __int_as_float(__float_as_int(y) | (__float_as_int(x) & 0x80000000));
}

// ---------------------------------------------------------------------------
// Prep kernels
// ---------------------------------------------------------------------------
__global__ void init_h0_kernel() {
    int i = blockIdx.x * blockDim.x + threadIdx.x;
    if (i < B_DIM * H_DIM) {
        g_h_hi[0][i] = __float2bfloat16(0.0f);
        g_h_lo[0][i] = __float2bfloat16(0.0f);
    }
    if (i < T_STEPS) g_bar[i] = 0u;       // reset grid-barrier counters each replay
}

__global__ __launch_bounds__(256) void split_x_kernel(const float* __restrict__ x) {
    size_t i = ((size_t)blockIdx.x * blockDim.x + threadIdx.x) * 4;
    float4 v = *(const float4*)(x + i);
    __nv_bfloat16 h0 = __float2bfloat16(v.x), h1 = __float2bfloat16(v.y);
    __nv_bfloat16 h2 = __float2bfloat16(v.z), h3 = __float2bfloat16(v.w);
    *(__nv_bfloat162*)(g_x_hi + i)     = __nv_bfloat162{h0, h1};
    *(__nv_bfloat162*)(g_x_hi + i + 2) = __nv_bfloat162{h2, h3};
    *(__nv_bfloat162*)(g_x_lo + i) = __nv_bfloat162{
        __float2bfloat16(v.x - __bfloat162float(h0)),
        __float2bfloat16(v.y - __bfloat162float(h1))};
    *(__nv_bfloat162*)(g_x_lo + i + 2) = __nv_bfloat162{
        __float2bfloat16(v.z - __bfloat162float(h2)),
        __float2bfloat16(v.w - __bfloat162float(h3))};
}

__global__ __launch_bounds__(256) void wsplit_kernel(
    const float* __restrict__ W, __nv_bfloat16* __restrict__ dh,
    __nv_bfloat16* __restrict__ dl)
{
    __shared__ float tile[32][33];
    int tx = threadIdx.x, ty = threadIdx.y;
    int k0 = blockIdx.y * 32;
    int n0 = blockIdx.x * 32;
    #pragma unroll
    for (int j = 0; j < 32; j += 8)
        tile[ty + j][tx] = W[(size_t)(k0 + ty + j) * H_DIM + n0 + tx];
    __syncthreads();
    #pragma unroll
    for (int j = 0; j < 32; j += 8) {
        float v = tile[tx][ty + j];
        __nv_bfloat16 hi = __float2bfloat16(v);
        __nv_bfloat16 lo = __float2bfloat16(v - __bfloat162float(hi));
        size_t idx = (size_t)(n0 + ty + j) * H_DIM + k0 + tx;
        dh[idx] = hi;
        dl[idx] = lo;
    }
}

// ---------------------------------------------------------------------------
// xproj = X @ W_in + bias  (split-bf16 HMMA, unchanged from round 3)
// ---------------------------------------------------------------------------
__global__ __launch_bounds__(256) void xproj_mma_kernel(const float* __restrict__ bias) {
    extern __shared__ char smem[];
    const uint32_t sb = smem_u32(smem);
    const int tid = threadIdx.x, wid = tid >> 5, lane = tid & 31;
    const int m0 = blockIdx.y * 128;
    const int n0 = blockIdx.x * 64;

    const __nv_bfloat16* __restrict__ Ah = g_x_hi;
    const __nv_bfloat16* __restrict__ Al = g_x_lo;
    const __nv_bfloat16* __restrict__ Bh = g_wi_hi + (size_t)n0 * H_DIM;
    const __nv_bfloat16* __restrict__ Bl = g_wi_lo + (size_t)n0 * H_DIM;

    float c[2][4][4];
    #pragma unroll
    for (int i = 0; i < 2; i++)
        #pragma unroll
        for (int j = 0; j < 4; j++)
            #pragma unroll
            for (int q = 0; q < 4; q++) c[i][j][q] = 0.0f;

    auto load_stage = [&](int s, int cch) {
        const int k0 = cch * KC;
        uint32_t base = sb + s * X_STG;
        #pragma unroll
        for (int j = 0; j < 4; j++) {
            int idx = tid + j * 256;
            int r = idx >> 3, kc = idx & 7;
            size_t go = (size_t)(m0 + r) * H_DIM + k0 + kc * 8;
            cp16(base + X_AH + r * ROWB + kc * 16, Ah + go);
            cp16(base + X_AL + r * ROWB + kc * 16, Al + go);
        }
        #pragma unroll
        for (int j = 0; j < 2; j++) {
            int idx = tid + j * 256;
            int r = idx >> 3, kc = idx & 7;
            size_t go = (size_t)r * H_DIM + k0 + kc * 8;
            cp16(base + X_BH + r * ROWB + kc * 16, Bh + go);
            cp16(base + X_BL + r * ROWB + kc * 16, Bl + go);
        }
        cp_commit();
    };

    const int mwb = (wid >> 1) * 32;
    const int nwb = (wid & 1) * 32;
    const uint32_t aOff = (uint32_t)((lane & 15) * ROWB + ((lane >> 4) * 8) * 2);
    const uint32_t bOff = (uint32_t)(((lane & 7) | ((lane >> 1) & 8)) * ROWB + (lane & 8) * 2);

    auto compute_stage = [&](int s) {
        uint32_t base = sb + s * X_STG;
        uint32_t aH = base + X_AH + mwb * ROWB + aOff;
        uint32_t aL = base + X_AL + mwb * ROWB + aOff;
        uint32_t bH = base + X_BH + nwb * ROWB + bOff;
        uint32_t bL = base + X_BL + nwb * ROWB + bOff;
        #pragma unroll
        for (int kk = 0; kk < KC / 16; kk++) {
            uint32_t ah[2][4], al[2][4], bh[8], bl[8];
            ldsm4(aH + kk * 32, ah[0]);
            ldsm4(aH + 16 * ROWB + kk * 32, ah[1]);
            ldsm4(aL + kk * 32, al[0]);
            ldsm4(aL + 16 * ROWB + kk * 32, al[1]);
            ldsm4(bH + kk * 32, bh);
            ldsm4(bH + 16 * ROWB + kk * 32, bh + 4);
            ldsm4(bL + kk * 32, bl);
            ldsm4(bL + 16 * ROWB + kk * 32, bl + 4);
            #pragma unroll
            for (int mi = 0; mi < 2; mi++)
                #pragma unroll
                for (int ni = 0; ni < 4; ni++) {
                    mma16816(c[mi][ni], ah[mi], bh[2 * ni], bh[2 * ni + 1]);
                    mma16816(c[mi][ni], ah[mi], bl[2 * ni], bl[2 * ni + 1]);
                    mma16816(c[mi][ni], al[mi], bh[2 * ni], bh[2 * ni + 1]);
                }
        }
    };

    load_stage(0, 0);
    #pragma unroll 1
    for (int cch = 0; cch < NCH; cch++) {
        if (cch + 1 < NCH) { load_stage((cch + 1) & 1, cch + 1); cp_wait1(); }
        else cp_wait0();
        __syncthreads();
        compute_stage(cch & 1);
        __syncthreads();
    }

    #pragma unroll
    for (int mi = 0; mi < 2; mi++)
        #pragma unroll
        for (int ni = 0; ni < 4; ni++) {
            int r  = m0 + mwb + mi * 16 + (lane >> 2);
            int cc = n0 + nwb + ni * 8 + 2 * (lane & 3);
            float bx = bias[cc], by = bias[cc + 1];
            size_t o0 = (size_t)r * H_DIM + cc;
            size_t o1 = o0 + (size_t)8 * H_DIM;
            *(float2*)(g_xproj + o0) = make_float2(c[mi][ni][0] + bx, c[mi][ni][1] + by);
            *(float2*)(g_xproj + o1) = make_float2(c[mi][ni][2] + bx, c[mi][ni][3] + by);
        }
}

// ---------------------------------------------------------------------------
// Persistent scan kernel: all 256 steps in ONE launch.
// Grid (64, 2) = 128 CTAs (1/SM), 128 threads (4 warps, 2m x 2n).
// CTA owns output tile: rows [mh*64, +64), cols [nt*32, +32).
// W_hi^T slice (32 x 2048) stays resident in SMEM for all steps.
// Per step: stream h hi/lo + W_lo chunks via cp.async double buffer,
//           3-product split-bf16 HMMA, tanh epilogue, grid spin barrier.
// ---------------------------------------------------------------------------
__global__ __launch_bounds__(128) void scan_kernel(float* __restrict__ final_out) {
    extern __shared__ char smem[];
    const uint32_t sb = smem_u32(smem);
    const int tid = threadIdx.x, wid = tid >> 5, lane = tid & 31;
    const int nt = blockIdx.x, mh = blockIdx.y;
    const int n0 = nt * 32;
    const int m0 = mh * 64;

    // ---- load resident W_hi^T slice (32 rows x 2048 k), pitch 4112 ----
    {
        const __nv_bfloat16* WHg = g_wr_hi + (size_t)n0 * H_DIM;
        #pragma unroll 4
        for (int idx = tid; idx < 32 * 256; idx += 128) {      // 16B units
            int r = idx >> 8, kc = idx & 255;
            cp16(sb + r * WPITCH + kc * 16, WHg + (size_t)r * H_DIM + kc * 8);
        }
        cp_commit();
        cp_wait0();
        __syncthreads();
    }

    const __nv_bfloat16* __restrict__ WLg = g_wr_lo + (size_t)n0 * H_DIM;

    // warp layout: wm = wid>>1 (m 32-block), wn = wid&1 (n 16-block)
    const int wm = wid >> 1, wn = wid & 1;
    const uint32_t aOff   = (uint32_t)((lane & 15) * ROWB + (lane >> 4) * 16);
    const uint32_t rowsel = (uint32_t)((lane & 7) | ((lane >> 1) & 8));
    const uint32_t bOffL  = rowsel * ROWB   + (lane & 8) * 2 + (uint32_t)(wn * 16) * ROWB;
    const uint32_t bOffH  = rowsel * WPITCH + (lane & 8) * 2 + (uint32_t)(wn * 16) * WPITCH;

    for (int t = 0; t < T_STEPS; t++) {
        const __nv_bfloat16* __restrict__ Ah = g_h_hi[t & 1] + (size_t)m0 * H_DIM;
        const __nv_bfloat16* __restrict__ Al = g_h_lo[t & 1] + (size_t)m0 * H_DIM;

        float c[2][2][4];
        #pragma unroll
        for (int i = 0; i < 2; i++)
            #pragma unroll
            for (int j = 0; j < 2; j++)
                #pragma unroll
                for (int q = 0; q < 4; q++) c[i][j][q] = 0.0f;

        auto load_stage = [&](int s, int cch) {
            const int k0 = cch * KC;
            uint32_t base = sb + WH_SZ + s * ST_SZ;
            #pragma unroll
            for (int j = 0; j < 4; j++) {          // A: 64 rows x 8 chunks, hi+lo
                int idx = tid + j * 128;
                int r = idx >> 3, kc = idx & 7;
                size_t go = (size_t)r * H_DIM + k0 + kc * 8;
                cp16(base + ST_AH + r * ROWB + kc * 16, Ah + go);
                cp16(base + ST_AL + r * ROWB + kc * 16, Al + go);
            }
            #pragma unroll
            for (int j = 0; j < 2; j++) {          // W_lo: 32 rows x 8 chunks
                int idx = tid + j * 128;
                int r = idx >> 3, kc = idx & 7;
                cp16(base + ST_WL + r * ROWB + kc * 16,
                     WLg + (size_t)r * H_DIM + k0 + kc * 8);
            }
            cp_commit();
        };

        auto compute_stage = [&](int s, int cch) {
            uint32_t base = sb + WH_SZ + s * ST_SZ;
            uint32_t aH = base + ST_AH + (uint32_t)(wm * 32) * ROWB + aOff;
            uint32_t aL = base + ST_AL + (uint32_t)(wm * 32) * ROWB + aOff;
            uint32_t bL = base + ST_WL + bOffL;
            uint32_t bH = sb + bOffH + (uint32_t)(cch * KC) * 2;
            #pragma unroll
            for (int kk = 0; kk < KC / 16; kk++) {
                uint32_t ah[2][4], al[2][4], bh[4], bl[4];
                ldsm4(aH + kk * 32, ah[0]);
                ldsm4(aH + 16 * ROWB + kk * 32, ah[1]);
                ldsm4(aL + kk * 32, al[0]);
                ldsm4(aL + 16 * ROWB + kk * 32, al[1]);
                ldsm4(bH + kk * 32, bh);
                ldsm4(bL + kk * 32, bl);
                #pragma unroll
                for (int mi = 0; mi < 2; mi++)
                    #pragma unroll
                    for (int ni = 0; ni < 2; ni++) {
                        mma16816(c[mi][ni], ah[mi], bh[2 * ni], bh[2 * ni + 1]);
                        mma16816(c[mi][ni], ah[mi], bl[2 * ni], bl[2 * ni + 1]);
                        mma16816(c[mi][ni], al[mi], bh[2 * ni], bh[2 * ni + 1]);
                    }
            }
        };

        load_stage(0, 0);
        #pragma unroll 1
        for (int cch = 0; cch < NCH; cch++) {
            if (cch + 1 < NCH) { load_stage((cch + 1) & 1, cch + 1); cp_wait1(); }
            else cp_wait0();
            __syncthreads();
            compute_stage(cch & 1, cch);
            __syncthreads();
        }

        // ---- epilogue: tanh(acc + xproj_t), write h splits (or final) ----
        const float* __restrict__ xp = g_xproj + (size_t)t * B_DIM * H_DIM;
        const bool last = (t == T_STEPS - 1);
        __nv_bfloat16* __restrict__ Hh = g_h_hi[(t + 1) & 1];
        __nv_bfloat16* __restrict__ Hl = g_h_lo[(t + 1) & 1];

        #pragma unroll
        for (int mi = 0; mi < 2; mi++)
            #pragma unroll
            for (int ni = 0; ni < 2; ni++) {
                int r  = m0 + wm * 32 + mi * 16 + (lane >> 2);
                int cc = n0 + wn * 16 + ni * 8 + 2 * (lane & 3);
                size_t o0 = (size_t)r * H_DIM + cc;
                size_t o1 = o0 + (size_t)8 * H_DIM;
                float2 x0 = *(const float2*)(xp + o0);
                float2 x1 = *(const float2*)(xp + o1);
                float v00 = fast_tanh(c[mi][ni][0] + x0.x);
                float v01 = fast_tanh(c[mi][ni][1] + x0.y);
                float v10 = fast_tanh(c[mi][ni][2] + x1.x);
                float v11 = fast_tanh(c[mi][ni][3] + x1.y);
                if (last) {
                    *(float2*)(final_out + o0) = make_float2(v00, v01);
                    *(float2*)(final_out + o1) = make_float2(v10, v11);
                } else {
                    __nv_bfloat16 h00 = __float2bfloat16(v00), h01 = __float2bfloat16(v01);
                    __nv_bfloat16 h10 = __float2bfloat16(v10), h11 = __float2bfloat16(v11);
                    *(__nv_bfloat162*)(Hh + o0) = __nv_bfloat162{h00, h01};
                    *(__nv_bfloat162*)(Hh + o1) = __nv_bfloat162{h10, h11};
                    *(__nv_bfloat162*)(Hl + o0) = __nv_bfloat162{
                        __float2bfloat16(v00 - __bfloat162float(h00)),
                        __float2bfloat16(v01 - __bfloat162float(h01))};
                    *(__nv_bfloat162*)(Hl + o1) = __nv_bfloat162{
                        __float2bfloat16(v10 - __bfloat162float(h10)),
                        __float2bfloat16(v11 - __bfloat162float(h11))};
                }
            }

        // ---- grid barrier (skip after final step) ----
        if (!last) {
            __syncthreads();
            if (tid == 0) {
                __threadfence();
                atomicAdd(&g_bar[t], 1u);
                volatile unsigned* bp = &g_bar[t];
                while (*bp < 128u) { __nanosleep(64); }
                __threadfence();
            }
            __syncthreads();
        }
    }
}

// ---------------------------------------------------------------------------
// Host launch — plain kernel launches only, graph-capturable
// ---------------------------------------------------------------------------
extern "C" void kernel_launch(void* const* d_in, const int* in_sizes, int n_in,
                              void* d_out, int out_size)
{
    const float* x     = (const float*)d_in[0];
    const float* w_in  = (const float*)d_in[1];
    const float* w_rec = (const float*)d_in[2];
    const float* bias  = (const float*)d_in[3];
    float* out = (float*)d_out;

    void *p_wr_h, *p_wr_l, *p_wi_h, *p_wi_l;
    cudaGetSymbolAddress(&p_wr_h, g_wr_hi);
    cudaGetSymbolAddress(&p_wr_l, g_wr_lo);
    cudaGetSymbolAddress(&p_wi_h, g_wi_hi);
    cudaGetSymbolAddress(&p_wi_l, g_wi_lo);

    cudaFuncSetAttribute(scan_kernel,
                         cudaFuncAttributeMaxDynamicSharedMemorySize, SMEM_SCAN);
    cudaFuncSetAttribute(xproj_mma_kernel,
                         cudaFuncAttributeMaxDynamicSharedMemorySize, 2 * X_STG);

    // prep
    init_h0_kernel<<<(B_DIM * H_DIM + 255) / 256, 256>>>();
    split_x_kernel<<<(int)(((size_t)T_STEPS * B_DIM * H_DIM) / 4 / 256), 256>>>(x);
    wsplit_kernel<<<dim3(H_DIM / 32, H_DIM / 32), dim3(32, 8)>>>(
        w_rec, (__nv_bfloat16*)p_wr_h, (__nv_bfloat16*)p_wr_l);
    wsplit_kernel<<<dim3(H_DIM / 32, H_DIM / 32), dim3(32, 8)>>>(
        w_in, (__nv_bfloat16*)p_wi_h, (__nv_bfloat16*)p_wi_l);

    // xproj (tensor-core)
    xproj_mma_kernel<<<dim3(H_DIM / 64, (T_STEPS * B_DIM) / 128), 256, 2 * X_STG>>>(bias);

    // persistent scan: all 256 steps in one launch
    scan_kernel<<<dim3(H_DIM / 32, B_DIM / 64), 128, SMEM_SCAN>>>(out);
}

// round 5
// speedup vs baseline: 3.7082x; 1.0882x over previous
#include <cuda_runtime.h>
#include <cuda_bf16.h>
#include <math.h>
#include <stdint.h>

#define T_STEPS 256
#define B_DIM   128
#define H_DIM   2048
#define KC      64                 // K elems per pipeline chunk
#define NCH     (H_DIM / KC)       // 32
#define ROWB    144                // padded smem row bytes for staged tiles

// ---- persistent scan kernel smem ----
#define WPITCH   4112              // 2048*2 + 16 pad: conflict-free ldsm rows
#define WH_SZ    (32 * WPITCH)     // 131584 B resident W_hi^T slice
#define ST_AH    0
#define ST_AL    9216
#define ST_WL    18432
#define ST_SZ    23040             // AH 9216 + AL 9216 + WL 4608
#define SMEM_SCAN (WH_SZ + 3 * ST_SZ)   // 200704 (3-stage)

// ---- xproj kernel smem (stage = 55296 B, 3 stages) ----
#define X_AH 0
#define X_AL 18432
#define X_BH 36864
#define X_BL 46080
#define X_STG 55296
#define SMEM_XPROJ (3 * X_STG)          // 165888

// ---------------------------------------------------------------------------
// Device scratch (no allocations allowed anywhere)
// ---------------------------------------------------------------------------
__device__ __align__(128) float g_xproj[(size_t)T_STEPS * B_DIM * H_DIM];   // 256 MB
__device__ __align__(128) __nv_bfloat16 g_h_hi[2][B_DIM * H_DIM];
__device__ __align__(128) __nv_bfloat16 g_h_lo[2][B_DIM * H_DIM];
__device__ __align__(128) __nv_bfloat16 g_wr_hi[(size_t)H_DIM * H_DIM];     // w_rec^T splits
__device__ __align__(128) __nv_bfloat16 g_wr_lo[(size_t)H_DIM * H_DIM];
__device__ __align__(128) __nv_bfloat16 g_wi_hi[(size_t)H_DIM * H_DIM];     // w_in^T splits
__device__ __align__(128) __nv_bfloat16 g_wi_lo[(size_t)H_DIM * H_DIM];
__device__ __align__(128) __nv_bfloat16 g_x_hi[(size_t)T_STEPS * B_DIM * H_DIM];
__device__ __align__(128) __nv_bfloat16 g_x_lo[(size_t)T_STEPS * B_DIM * H_DIM];
__device__ unsigned g_bar[T_STEPS];                                          // grid barrier counters

// ---------------------------------------------------------------------------
// PTX helpers — legal on plain sm_103 target
// ---------------------------------------------------------------------------
__device__ __forceinline__ uint32_t smem_u32(const void* p) {
    uint32_t a;
    asm("{ .reg .u64 t; cvta.to.shared.u64 t, %1; cvt.u32.u64 %0, t; }"
        : "=r"(a) : "l"(p));
    return a;
}
__device__ __forceinline__ void cp16(uint32_t dst, const void* src) {
    asm volatile("cp.async.cg.shared.global [%0], [%1], 16;"
                 :: "r"(dst), "l"(src) : "memory");
}
__device__ __forceinline__ void cp_commit() {
    asm volatile("cp.async.commit_group;" ::: "memory");
}
__device__ __forceinline__ void cp_wait1() {
    asm volatile("cp.async.wait_group 1;" ::: "memory");
}
__device__ __forceinline__ void cp_wait0() {
    asm volatile("cp.async.wait_group 0;" ::: "memory");
}
__device__ __forceinline__ void ldsm4(uint32_t addr, uint32_t r[4]) {
    asm volatile("ldmatrix.sync.aligned.m8n8.x4.shared.b16 {%0,%1,%2,%3}, [%4];"
                 : "=r"(r[0]), "=r"(r[1]), "=r"(r[2]), "=r"(r[3]) : "r"(addr));
}
__device__ __forceinline__ void mma16816(float c[4], const uint32_t a[4],
                                         uint32_t b0, uint32_t b1) {
    asm volatile("mma.sync.aligned.m16n8k16.row.col.f32.bf16.bf16.f32 "
                 "{%0,%1,%2,%3},{%4,%5,%6,%7},{%8,%9},{%0,%1,%2,%3};"
                 : "+f"(c[0]), "+f"(c[1]), "+f"(c[2]), "+f"(c[3])
                 : "r"(a[0]), "r"(a[1]), "r"(a[2]), "r"(a[3]), "r"(b0), "r"(b1));
}

// ---------------------------------------------------------------------------
// FMA-only accurate tanh, |err| ~2e-7
// ---------------------------------------------------------------------------
__device__ __forceinline__ float fast_tanh(float x) {
    float ax = fminf(fabsf(x), 9.0f);
    float t  = ax * 2.8853900817779268f;
    float f  = t + 12582912.0f;
    int   n  = __float_as_int(f) - 0x4B400000;
    float r  = t - (f - 12582912.0f);
    float p = 1.5403530e-4f;
    p = fmaf(p, r, 1.3333558e-3f);
    p = fmaf(p, r, 9.6181291e-3f);
    p = fmaf(p, r, 5.5504109e-2f);
    p = fmaf(p, r, 2.4022651e-1f);
    p = fmaf(p, r, 6.9314718e-1f);
    p = fmaf(p, r, 1.0f);
    float e2x = p * __int_as_float((n + 127) << 23);
    float d = e2x + 1.0f;
    float rc = __int_as_float(0x7EF311C3 - __float_as_int(d));
    rc = rc * fmaf(-d, rc, 2.0f);
    rc = rc * fmaf(-d, rc, 2.0f);
    rc = rc * fmaf(-d, rc, 2.0f);
    float y = fmaf(-2.0f, rc, 1.0f);
    return __int_as_float(__float_as_int(y) | (__float_as_int(x) & 0x80000000));
}

// ---------------------------------------------------------------------------
// Prep kernels
// ---------------------------------------------------------------------------
__global__ void init_h0_kernel() {
    int i = blockIdx.x * blockDim.x + threadIdx.x;
    if (i < B_DIM * H_DIM) {
        g_h_hi[0][i] = __float2bfloat16(0.0f);
        g_h_lo[0][i] = __float2bfloat16(0.0f);
    }
    if (i < T_STEPS) g_bar[i] = 0u;       // reset grid-barrier counters each replay
}

__global__ __launch_bounds__(256) void split_x_kernel(const float* __restrict__ x) {
    size_t i = ((size_t)blockIdx.x * blockDim.x + threadIdx.x) * 4;
    float4 v = *(const float4*)(x + i);
    __nv_bfloat16 h0 = __float2bfloat16(v.x), h1 = __float2bfloat16(v.y);
    __nv_bfloat16 h2 = __float2bfloat16(v.z), h3 = __float2bfloat16(v.w);
    *(__nv_bfloat162*)(g_x_hi + i)     = __nv_bfloat162{h0, h1};
    *(__nv_bfloat162*)(g_x_hi + i + 2) = __nv_bfloat162{h2, h3};
    *(__nv_bfloat162*)(g_x_lo + i) = __nv_bfloat162{
        __float2bfloat16(v.x - __bfloat162float(h0)),
        __float2bfloat16(v.y - __bfloat162float(h1))};
    *(__nv_bfloat162*)(g_x_lo + i + 2) = __nv_bfloat162{
        __float2bfloat16(v.z - __bfloat162float(h2)),
        __float2bfloat16(v.w - __bfloat162float(h3))};
}

__global__ __launch_bounds__(256) void wsplit_kernel(
    const float* __restrict__ W, __nv_bfloat16* __restrict__ dh,
    __nv_bfloat16* __restrict__ dl)
{
    __shared__ float tile[32][33];
    int tx = threadIdx.x, ty = threadIdx.y;
    int k0 = blockIdx.y * 32;
    int n0 = blockIdx.x * 32;
    #pragma unroll
    for (int j = 0; j < 32; j += 8)
        tile[ty + j][tx] = W[(size_t)(k0 + ty + j) * H_DIM + n0 + tx];
    __syncthreads();
    #pragma unroll
    for (int j = 0; j < 32; j += 8) {
        float v = tile[tx][ty + j];
        __nv_bfloat16 hi = __float2bfloat16(v);
        __nv_bfloat16 lo = __float2bfloat16(v - __bfloat162float(hi));
        size_t idx = (size_t)(n0 + ty + j) * H_DIM + k0 + tx;
        dh[idx] = hi;
        dl[idx] = lo;
    }
}

// ---------------------------------------------------------------------------
// xproj = X @ W_in + bias  (split-bf16 HMMA, 3-stage / 1-sync pipeline)
// CTA tile 128x64, 8 warps (4x2), warp tile 32x32. Grid (32, 256).
// ---------------------------------------------------------------------------
__global__ __launch_bounds__(256) void xproj_mma_kernel(const float* __restrict__ bias) {
    extern __shared__ char smem[];
    const uint32_t sb = smem_u32(smem);
    const int tid = threadIdx.x, wid = tid >> 5, lane = tid & 31;
    const int m0 = blockIdx.y * 128;
    const int n0 = blockIdx.x * 64;

    const __nv_bfloat16* __restrict__ Ah = g_x_hi;
    const __nv_bfloat16* __restrict__ Al = g_x_lo;
    const __nv_bfloat16* __restrict__ Bh = g_wi_hi + (size_t)n0 * H_DIM;
    const __nv_bfloat16* __restrict__ Bl = g_wi_lo + (size_t)n0 * H_DIM;

    float c[2][4][4];
    #pragma unroll
    for (int i = 0; i < 2; i++)
        #pragma unroll
        for (int j = 0; j < 4; j++)
            #pragma unroll
            for (int q = 0; q < 4; q++) c[i][j][q] = 0.0f;

    auto load_stage = [&](int s, int cch) {
        const int k0 = cch * KC;
        uint32_t base = sb + s * X_STG;
        #pragma unroll
        for (int j = 0; j < 4; j++) {
            int idx = tid + j * 256;
            int r = idx >> 3, kc = idx & 7;
            size_t go = (size_t)(m0 + r) * H_DIM + k0 + kc * 8;
            cp16(base + X_AH + r * ROWB + kc * 16, Ah + go);
            cp16(base + X_AL + r * ROWB + kc * 16, Al + go);
        }
        #pragma unroll
        for (int j = 0; j < 2; j++) {
            int idx = tid + j * 256;
            int r = idx >> 3, kc = idx & 7;
            size_t go = (size_t)r * H_DIM + k0 + kc * 8;
            cp16(base + X_BH + r * ROWB + kc * 16, Bh + go);
            cp16(base + X_BL + r * ROWB + kc * 16, Bl + go);
        }
        cp_commit();
    };

    const int mwb = (wid >> 1) * 32;
    const int nwb = (wid & 1) * 32;
    const uint32_t aOff = (uint32_t)((lane & 15) * ROWB + ((lane >> 4) * 8) * 2);
    const uint32_t bOff = (uint32_t)(((lane & 7) | ((lane >> 1) & 8)) * ROWB + (lane & 8) * 2);

    auto compute_stage = [&](int s) {
        uint32_t base = sb + s * X_STG;
        uint32_t aH = base + X_AH + mwb * ROWB + aOff;
        uint32_t aL = base + X_AL + mwb * ROWB + aOff;
        uint32_t bH = base + X_BH + nwb * ROWB + bOff;
        uint32_t bL = base + X_BL + nwb * ROWB + bOff;
        #pragma unroll
        for (int kk = 0; kk < KC / 16; kk++) {
            uint32_t ah[2][4], al[2][4], bh[8], bl[8];
            ldsm4(aH + kk * 32, ah[0]);
            ldsm4(aH + 16 * ROWB + kk * 32, ah[1]);
            ldsm4(aL + kk * 32, al[0]);
            ldsm4(aL + 16 * ROWB + kk * 32, al[1]);
            ldsm4(bH + kk * 32, bh);
            ldsm4(bH + 16 * ROWB + kk * 32, bh + 4);
            ldsm4(bL + kk * 32, bl);
            ldsm4(bL + 16 * ROWB + kk * 32, bl + 4);
            #pragma unroll
            for (int mi = 0; mi < 2; mi++)
                #pragma unroll
                for (int ni = 0; ni < 4; ni++) {
                    mma16816(c[mi][ni], ah[mi], bh[2 * ni], bh[2 * ni + 1]);
                    mma16816(c[mi][ni], ah[mi], bl[2 * ni], bl[2 * ni + 1]);
                    mma16816(c[mi][ni], al[mi], bh[2 * ni], bh[2 * ni + 1]);
                }
        }
    };

    // 3-stage, one sync per chunk (CUTLASS multistage ordering)
    load_stage(0, 0);
    load_stage(1, 1);
    #pragma unroll 1
    for (int cch = 0; cch < NCH; cch++) {
        if (cch == NCH - 1) cp_wait0(); else cp_wait1();
        __syncthreads();
        if (cch + 2 < NCH) load_stage((cch + 2) % 3, cch + 2);
        compute_stage(cch % 3);
    }

    #pragma unroll
    for (int mi = 0; mi < 2; mi++)
        #pragma unroll
        for (int ni = 0; ni < 4; ni++) {
            int r  = m0 + mwb + mi * 16 + (lane >> 2);
            int cc = n0 + nwb + ni * 8 + 2 * (lane & 3);
            float bx = bias[cc], by = bias[cc + 1];
            size_t o0 = (size_t)r * H_DIM + cc;
            size_t o1 = o0 + (size_t)8 * H_DIM;
            *(float2*)(g_xproj + o0) = make_float2(c[mi][ni][0] + bx, c[mi][ni][1] + by);
            *(float2*)(g_xproj + o1) = make_float2(c[mi][ni][2] + bx, c[mi][ni][3] + by);
        }
}

// ---------------------------------------------------------------------------
// Persistent scan kernel: all 256 steps in ONE launch.
// Grid (64, 2) = 128 CTAs, 128 threads (4 warps, 2m x 2n).
// W_hi^T slice resident in SMEM; h hi/lo + W_lo streamed via 3-stage
// cp.async pipeline with one __syncthreads per chunk; xproj prefetched to
// registers before the K-loop; release/acquire grid barrier per step.
// ---------------------------------------------------------------------------
__global__ __launch_bounds__(128) void scan_kernel(float* __restrict__ final_out) {
    extern __shared__ char smem[];
    const uint32_t sb = smem_u32(smem);
    const int tid = threadIdx.x, wid = tid >> 5, lane = tid & 31;
    const int nt = blockIdx.x, mh = blockIdx.y;
    const int n0 = nt * 32;
    const int m0 = mh * 64;

    // ---- load resident W_hi^T slice (32 rows x 2048 k), pitch 4112 ----
    {
        const __nv_bfloat16* WHg = g_wr_hi + (size_t)n0 * H_DIM;
        #pragma unroll 4
        for (int idx = tid; idx < 32 * 256; idx += 128) {      // 16B units
            int r = idx >> 8, kc = idx & 255;
            cp16(sb + r * WPITCH + kc * 16, WHg + (size_t)r * H_DIM + kc * 8);
        }
        cp_commit();
        cp_wait0();
        __syncthreads();
    }

    const __nv_bfloat16* __restrict__ WLg = g_wr_lo + (size_t)n0 * H_DIM;

    const int wm = wid >> 1, wn = wid & 1;
    const uint32_t aOff   = (uint32_t)((lane & 15) * ROWB + (lane >> 4) * 16);
    const uint32_t rowsel = (uint32_t)((lane & 7) | ((lane >> 1) & 8));
    const uint32_t bOffL  = rowsel * ROWB   + (lane & 8) * 2 + (uint32_t)(wn * 16) * ROWB;
    const uint32_t bOffH  = rowsel * WPITCH + (lane & 8) * 2 + (uint32_t)(wn * 16) * WPITCH;

    // fixed epilogue coordinates for this thread
    const int er  = m0 + wm * 32 + (lane >> 2);        // +0 / +8 / +16 / +24 row offsets
    const int ecc = n0 + wn * 16 + 2 * (lane & 3);     // +0 / +8 col offsets

    for (int t = 0; t < T_STEPS; t++) {
        const __nv_bfloat16* __restrict__ Ah = g_h_hi[t & 1] + (size_t)m0 * H_DIM;
        const __nv_bfloat16* __restrict__ Al = g_h_lo[t & 1] + (size_t)m0 * H_DIM;
        const float* __restrict__ xp = g_xproj + (size_t)t * B_DIM * H_DIM;

        // ---- prefetch xproj fragment (independent of h) into registers ----
        float2 xf[2][2][2];
        #pragma unroll
        for (int mi = 0; mi < 2; mi++)
            #pragma unroll
            for (int ni = 0; ni < 2; ni++) {
                size_t o0 = (size_t)(er + mi * 16) * H_DIM + ecc + ni * 8;
                xf[mi][ni][0] = __ldg((const float2*)(xp + o0));
                xf[mi][ni][1] = __ldg((const float2*)(xp + o0 + (size_t)8 * H_DIM));
            }

        float c[2][2][4];
        #pragma unroll
        for (int i = 0; i < 2; i++)
            #pragma unroll
            for (int j = 0; j < 2; j++)
                #pragma unroll
                for (int q = 0; q < 4; q++) c[i][j][q] = 0.0f;

        auto load_stage = [&](int s, int cch) {
            const int k0 = cch * KC;
            uint32_t base = sb + WH_SZ + s * ST_SZ;
            #pragma unroll
            for (int j = 0; j < 4; j++) {          // A: 64 rows x 8 chunks, hi+lo
                int idx = tid + j * 128;
                int r = idx >> 3, kc = idx & 7;
                size_t go = (size_t)r * H_DIM + k0 + kc * 8;
                cp16(base + ST_AH + r * ROWB + kc * 16, Ah + go);
                cp16(base + ST_AL + r * ROWB + kc * 16, Al + go);
            }
            #pragma unroll
            for (int j = 0; j < 2; j++) {          // W_lo: 32 rows x 8 chunks
                int idx = tid + j * 128;
                int r = idx >> 3, kc = idx & 7;
                cp16(base + ST_WL + r * ROWB + kc * 16,
                     WLg + (size_t)r * H_DIM + k0 + kc * 8);
            }
            cp_commit();
        };

        auto compute_stage = [&](int s, int cch) {
            uint32_t base = sb + WH_SZ + s * ST_SZ;
            uint32_t aH = base + ST_AH + (uint32_t)(wm * 32) * ROWB + aOff;
            uint32_t aL = base + ST_AL + (uint32_t)(wm * 32) * ROWB + aOff;
            uint32_t bL = base + ST_WL + bOffL;
            uint32_t bH = sb + bOffH + (uint32_t)(cch * KC) * 2;
            #pragma unroll
            for (int kk = 0; kk < KC / 16; kk++) {
                uint32_t ah[2][4], al[2][4], bh[4], bl[4];
                ldsm4(aH + kk * 32, ah[0]);
                ldsm4(aH + 16 * ROWB + kk * 32, ah[1]);
                ldsm4(aL + kk * 32, al[0]);
                ldsm4(aL + 16 * ROWB + kk * 32, al[1]);
                ldsm4(bH + kk * 32, bh);
                ldsm4(bL + kk * 32, bl);
                #pragma unroll
                for (int mi = 0; mi < 2; mi++)
                    #pragma unroll
                    for (int ni = 0; ni < 2; ni++) {
                        mma16816(c[mi][ni], ah[mi], bh[2 * ni], bh[2 * ni + 1]);
                        mma16816(c[mi][ni], ah[mi], bl[2 * ni], bl[2 * ni + 1]);
                        mma16816(c[mi][ni], al[mi], bh[2 * ni], bh[2 * ni + 1]);
                    }
            }
        };

        // ---- 3-stage pipeline, one sync per chunk ----
        load_stage(0, 0);
        load_stage(1, 1);
        #pragma unroll 1
        for (int cch = 0; cch < NCH; cch++) {
            if (cch == NCH - 1) cp_wait0(); else cp_wait1();
            __syncthreads();
            if (cch + 2 < NCH) load_stage((cch + 2) % 3, cch + 2);
            compute_stage(cch % 3, cch);
        }

        // ---- epilogue: tanh(acc + xproj_t), write h splits (or final) ----
        const bool last = (t == T_STEPS - 1);
        __nv_bfloat16* __restrict__ Hh = g_h_hi[(t + 1) & 1];
        __nv_bfloat16* __restrict__ Hl = g_h_lo[(t + 1) & 1];

        #pragma unroll
        for (int mi = 0; mi < 2; mi++)
            #pragma unroll
            for (int ni = 0; ni < 2; ni++) {
                size_t o0 = (size_t)(er + mi * 16) * H_DIM + ecc + ni * 8;
                size_t o1 = o0 + (size_t)8 * H_DIM;
                float2 x0 = xf[mi][ni][0];
                float2 x1 = xf[mi][ni][1];
                float v00 = fast_tanh(c[mi][ni][0] + x0.x);
                float v01 = fast_tanh(c[mi][ni][1] + x0.y);
                float v10 = fast_tanh(c[mi][ni][2] + x1.x);
                float v11 = fast_tanh(c[mi][ni][3] + x1.y);
                if (last) {
                    *(float2*)(final_out + o0) = make_float2(v00, v01);
                    *(float2*)(final_out + o1) = make_float2(v10, v11);
                } else {
                    __nv_bfloat16 h00 = __float2bfloat16(v00), h01 = __float2bfloat16(v01);
                    __nv_bfloat16 h10 = __float2bfloat16(v10), h11 = __float2bfloat16(v11);
                    *(__nv_bfloat162*)(Hh + o0) = __nv_bfloat162{h00, h01};
                    *(__nv_bfloat162*)(Hh + o1) = __nv_bfloat162{h10, h11};
                    *(__nv_bfloat162*)(Hl + o0) = __nv_bfloat162{
                        __float2bfloat16(v00 - __bfloat162float(h00)),
                        __float2bfloat16(v01 - __bfloat162float(h01))};
                    *(__nv_bfloat162*)(Hl + o1) = __nv_bfloat162{
                        __float2bfloat16(v10 - __bfloat162float(h10)),
                        __float2bfloat16(v11 - __bfloat162float(h11))};
                }
            }

        // ---- grid barrier: release/acquire, no full fences ----
        if (!last) {
            __syncthreads();
            if (tid == 0) {
                asm volatile("red.release.gpu.global.add.u32 [%0], %1;"
                             :: "l"(&g_bar[t]), "r"(1u) : "memory");
                unsigned v;
                do {
                    asm volatile("ld.acquire.gpu.global.u32 %0, [%1];"
                                 : "=r"(v) : "l"(&g_bar[t]) : "memory");
                } while (v < 128u);
            }
            __syncthreads();
        }
    }
}

// ---------------------------------------------------------------------------
// Host launch — plain kernel launches only, graph-capturable
// ---------------------------------------------------------------------------
extern "C" void kernel_launch(void* const* d_in, const int* in_sizes, int n_in,
                              void* d_out, int out_size)
{
    const float* x     = (const float*)d_in[0];
    const float* w_in  = (const float*)d_in[1];
    const float* w_rec = (const float*)d_in[2];
    const float* bias  = (const float*)d_in[3];
    float* out = (float*)d_out;

    void *p_wr_h, *p_wr_l, *p_wi_h, *p_wi_l;
    cudaGetSymbolAddress(&p_wr_h, g_wr_hi);
    cudaGetSymbolAddress(&p_wr_l, g_wr_lo);
    cudaGetSymbolAddress(&p_wi_h, g_wi_hi);
    cudaGetSymbolAddress(&p_wi_l, g_wi_lo);

    cudaFuncSetAttribute(scan_kernel,
                         cudaFuncAttributeMaxDynamicSharedMemorySize, SMEM_SCAN);
    cudaFuncSetAttribute(xproj_mma_kernel,
                         cudaFuncAttributeMaxDynamicSharedMemorySize, SMEM_XPROJ);

    // prep
    init_h0_kernel<<<(B_DIM * H_DIM + 255) / 256, 256>>>();
    split_x_kernel<<<(int)(((size_t)T_STEPS * B_DIM * H_DIM) / 4 / 256), 256>>>(x);
    wsplit_kernel<<<dim3(H_DIM / 32, H_DIM / 32), dim3(32, 8)>>>(
        w_rec, (__nv_bfloat16*)p_wr_h, (__nv_bfloat16*)p_wr_l);
    wsplit_kernel<<<dim3(H_DIM / 32, H_DIM / 32), dim3(32, 8)>>>(
        w_in, (__nv_bfloat16*)p_wi_h, (__nv_bfloat16*)p_wi_l);

    // xproj (tensor-core)
    xproj_mma_kernel<<<dim3(H_DIM / 64, (T_STEPS * B_DIM) / 128), 256, SMEM_XPROJ>>>(bias);

    // persistent scan: all 256 steps in one launch
    scan_kernel<<<dim3(H_DIM / 32, B_DIM / 64), 128, SMEM_SCAN>>>(out);
}

// round 6
// speedup vs baseline: 4.8754x; 1.3147x over previous
#include <cuda_runtime.h>
#include <cuda_fp16.h>
#include <math.h>
#include <stdint.h>

#define T_STEPS 256
#define B_DIM   128
#define H_DIM   2048
#define KC      64                 // K elems per pipeline chunk
#define NCH     (H_DIM / KC)       // 32
#define ROWB    144                // padded smem row bytes for staged tiles

// ---- persistent scan kernel smem ----
#define WPITCH   4112              // 2048*2 + 16 pad: conflict-free ldsm rows
#define WH_SZ    (32 * WPITCH)     // 131584 B resident W_hi^T slice (fp16)
#define ST_A     0                 // h tile (fp16, single): 64*144 = 9216
#define ST_WL    9216              // W_lo tile: 32*144 = 4608
#define ST_SZ    13824
#define SMEM_SCAN (WH_SZ + 3 * ST_SZ)   // 173056 (3-stage)

// ---- xproj kernel smem ----
#define X_A   0                    // x tile (fp16, single): 128*144 = 18432
#define X_BH  18432                // W_in hi: 64*144 = 9216
#define X_BL  27648                // W_in lo: 9216
#define X_STG 36864
#define SMEM_XPROJ (3 * X_STG)     // 110592

// ---------------------------------------------------------------------------
// Device scratch (no allocations allowed anywhere)
// ---------------------------------------------------------------------------
__device__ __align__(128) float  g_xproj[(size_t)T_STEPS * B_DIM * H_DIM];  // 256 MB
__device__ __align__(128) __half g_h[2][B_DIM * H_DIM];                     // fp16 hidden
__device__ __align__(128) __half g_wr_hi[(size_t)H_DIM * H_DIM];            // w_rec^T splits
__device__ __align__(128) __half g_wr_lo[(size_t)H_DIM * H_DIM];
__device__ __align__(128) __half g_wi_hi[(size_t)H_DIM * H_DIM];            // w_in^T splits
__device__ __align__(128) __half g_wi_lo[(size_t)H_DIM * H_DIM];
__device__ __align__(128) __half g_x[(size_t)T_STEPS * B_DIM * H_DIM];      // x fp16
__device__ unsigned g_bar[2 * T_STEPS];                                     // per-(t, mh) counters

// ---------------------------------------------------------------------------
// PTX helpers — legal on plain sm_103 target
// ---------------------------------------------------------------------------
__device__ __forceinline__ uint32_t smem_u32(const void* p) {
    uint32_t a;
    asm("{ .reg .u64 t; cvta.to.shared.u64 t, %1; cvt.u32.u64 %0, t; }"
        : "=r"(a) : "l"(p));
    return a;
}
__device__ __forceinline__ void cp16(uint32_t dst, const void* src) {
    asm volatile("cp.async.cg.shared.global [%0], [%1], 16;"
                 :: "r"(dst), "l"(src) : "memory");
}
__device__ __forceinline__ void cp_commit() {
    asm volatile("cp.async.commit_group;" ::: "memory");
}
__device__ __forceinline__ void cp_wait1() {
    asm volatile("cp.async.wait_group 1;" ::: "memory");
}
__device__ __forceinline__ void cp_wait0() {
    asm volatile("cp.async.wait_group 0;" ::: "memory");
}
__device__ __forceinline__ void ldsm4(uint32_t addr, uint32_t r[4]) {
    asm volatile("ldmatrix.sync.aligned.m8n8.x4.shared.b16 {%0,%1,%2,%3}, [%4];"
                 : "=r"(r[0]), "=r"(r[1]), "=r"(r[2]), "=r"(r[3]) : "r"(addr));
}
__device__ __forceinline__ void mma16816(float c[4], const uint32_t a[4],
                                         uint32_t b0, uint32_t b1) {
    asm volatile("mma.sync.aligned.m16n8k16.row.col.f32.f16.f16.f32 "
                 "{%0,%1,%2,%3},{%4,%5,%6,%7},{%8,%9},{%0,%1,%2,%3};"
                 : "+f"(c[0]), "+f"(c[1]), "+f"(c[2]), "+f"(c[3])
                 : "r"(a[0]), "r"(a[1]), "r"(a[2]), "r"(a[3]), "r"(b0), "r"(b1));
}

// ---------------------------------------------------------------------------
// FMA-only accurate tanh, |err| ~2e-7
// ---------------------------------------------------------------------------
__device__ __forceinline__ float fast_tanh(float x) {
    float ax = fminf(fabsf(x), 9.0f);
    float t  = ax * 2.8853900817779268f;
    float f  = t + 12582912.0f;
    int   n  = __float_as_int(f) - 0x4B400000;
    float r  = t - (f - 12582912.0f);
    float p = 1.5403530e-4f;
    p = fmaf(p, r, 1.3333558e-3f);
    p = fmaf(p, r, 9.6181291e-3f);
    p = fmaf(p, r, 5.5504109e-2f);
    p = fmaf(p, r, 2.4022651e-1f);
    p = fmaf(p, r, 6.9314718e-1f);
    p = fmaf(p, r, 1.0f);
    float e2x = p * __int_as_float((n + 127) << 23);
    float d = e2x + 1.0f;
    float rc = __int_as_float(0x7EF311C3 - __float_as_int(d));
    rc = rc * fmaf(-d, rc, 2.0f);
    rc = rc * fmaf(-d, rc, 2.0f);
    rc = rc * fmaf(-d, rc, 2.0f);
    float y = fmaf(-2.0f, rc, 1.0f);
    return __int_as_float(__float_as_int(y) | (__float_as_int(x) & 0x80000000));
}

// ---------------------------------------------------------------------------
// Prep kernels
// ---------------------------------------------------------------------------
__global__ void init_h0_kernel() {
    int i = blockIdx.x * blockDim.x + threadIdx.x;
    if (i < B_DIM * H_DIM) g_h[0][i] = __float2half(0.0f);
    if (i < 2 * T_STEPS) g_bar[i] = 0u;
}

// x (fp32) -> fp16, 8 elems per thread
__global__ __launch_bounds__(256) void conv_x_kernel(const float* __restrict__ x) {
    size_t i = ((size_t)blockIdx.x * blockDim.x + threadIdx.x) * 8;
    float4 v0 = *(const float4*)(x + i);
    float4 v1 = *(const float4*)(x + i + 4);
    __half2 h0 = __floats2half2_rn(v0.x, v0.y);
    __half2 h1 = __floats2half2_rn(v0.z, v0.w);
    __half2 h2 = __floats2half2_rn(v1.x, v1.y);
    __half2 h3 = __floats2half2_rn(v1.z, v1.w);
    *(uint4*)(g_x + i) = make_uint4(
        *(uint32_t*)&h0, *(uint32_t*)&h1, *(uint32_t*)&h2, *(uint32_t*)&h3);
}

// W (k,n) fp32 -> W^T (n,k) fp16 hi/lo splits. 32x32 tiles.
__global__ __launch_bounds__(256) void wsplit_kernel(
    const float* __restrict__ W, __half* __restrict__ dh, __half* __restrict__ dl)
{
    __shared__ float tile[32][33];
    int tx = threadIdx.x, ty = threadIdx.y;
    int k0 = blockIdx.y * 32;
    int n0 = blockIdx.x * 32;
    #pragma unroll
    for (int j = 0; j < 32; j += 8)
        tile[ty + j][tx] = W[(size_t)(k0 + ty + j) * H_DIM + n0 + tx];
    __syncthreads();
    #pragma unroll
    for (int j = 0; j < 32; j += 8) {
        float v = tile[tx][ty + j];
        __half hi = __float2half(v);
        __half lo = __float2half(v - __half2float(hi));
        size_t idx = (size_t)(n0 + ty + j) * H_DIM + k0 + tx;
        dh[idx] = hi;
        dl[idx] = lo;
    }
}

// ---------------------------------------------------------------------------
// xproj = X @ W_in + bias  (fp16 2-product HMMA, 3-stage pipeline)
// CTA tile 128x64, 8 warps (4m x 2n), warp tile 32x32. Grid (32, 256).
// ---------------------------------------------------------------------------
__global__ __launch_bounds__(256) void xproj_mma_kernel(const float* __restrict__ bias) {
    extern __shared__ char smem[];
    const uint32_t sb = smem_u32(smem);
    const int tid = threadIdx.x, wid = tid >> 5, lane = tid & 31;
    const int m0 = blockIdx.y * 128;
    const int n0 = blockIdx.x * 64;

    const __half* __restrict__ A  = g_x + (size_t)m0 * H_DIM;
    const __half* __restrict__ Bh = g_wi_hi + (size_t)n0 * H_DIM;
    const __half* __restrict__ Bl = g_wi_lo + (size_t)n0 * H_DIM;

    float c[2][4][4];
    #pragma unroll
    for (int i = 0; i < 2; i++)
        #pragma unroll
        for (int j = 0; j < 4; j++)
            #pragma unroll
            for (int q = 0; q < 4; q++) c[i][j][q] = 0.0f;

    auto load_stage = [&](int s, int cch) {
        const int k0 = cch * KC;
        uint32_t base = sb + s * X_STG;
        #pragma unroll
        for (int j = 0; j < 4; j++) {              // A: 128 rows x 8 chunks
            int idx = tid + j * 256;
            int r = idx >> 3, kc = idx & 7;
            cp16(base + X_A + r * ROWB + kc * 16, A + (size_t)r * H_DIM + k0 + kc * 8);
        }
        #pragma unroll
        for (int j = 0; j < 2; j++) {              // B hi+lo: 64 rows x 8 chunks
            int idx = tid + j * 256;
            int r = idx >> 3, kc = idx & 7;
            size_t go = (size_t)r * H_DIM + k0 + kc * 8;
            cp16(base + X_BH + r * ROWB + kc * 16, Bh + go);
            cp16(base + X_BL + r * ROWB + kc * 16, Bl + go);
        }
        cp_commit();
    };

    const int mwb = (wid >> 1) * 32;
    const int nwb = (wid & 1) * 32;
    const uint32_t aOff = (uint32_t)((lane & 15) * ROWB + (lane >> 4) * 16);
    const uint32_t bOff = (uint32_t)(((lane & 7) | ((lane >> 1) & 8)) * ROWB + (lane & 8) * 2);

    auto compute_stage = [&](int s) {
        uint32_t base = sb + s * X_STG;
        uint32_t aA = base + X_A  + mwb * ROWB + aOff;
        uint32_t bH = base + X_BH + nwb * ROWB + bOff;
        uint32_t bL = base + X_BL + nwb * ROWB + bOff;
        uint32_t ah[2][2][4], bh[2][8], bl[2][8];
        ldsm4(aA, ah[0][0]);
        ldsm4(aA + 16 * ROWB, ah[0][1]);
        ldsm4(bH, bh[0]);
        ldsm4(bH + 16 * ROWB, bh[0] + 4);
        ldsm4(bL, bl[0]);
        ldsm4(bL + 16 * ROWB, bl[0] + 4);
        #pragma unroll
        for (int kk = 0; kk < KC / 16; kk++) {
            int cur = kk & 1, nxt = cur ^ 1;
            if (kk + 1 < KC / 16) {                // prefetch next k16 fragments
                ldsm4(aA + (kk + 1) * 32, ah[nxt][0]);
                ldsm4(aA + 16 * ROWB + (kk + 1) * 32, ah[nxt][1]);
                ldsm4(bH + (kk + 1) * 32, bh[nxt]);
                ldsm4(bH + 16 * ROWB + (kk + 1) * 32, bh[nxt] + 4);
                ldsm4(bL + (kk + 1) * 32, bl[nxt]);
                ldsm4(bL + 16 * ROWB + (kk + 1) * 32, bl[nxt] + 4);
            }
            #pragma unroll
            for (int mi = 0; mi < 2; mi++)
                #pragma unroll
                for (int ni = 0; ni < 4; ni++) {
                    mma16816(c[mi][ni], ah[cur][mi], bh[cur][2 * ni], bh[cur][2 * ni + 1]);
                    mma16816(c[mi][ni], ah[cur][mi], bl[cur][2 * ni], bl[cur][2 * ni + 1]);
                }
        }
    };

    load_stage(0, 0);
    load_stage(1, 1);
    #pragma unroll 1
    for (int cch = 0; cch < NCH; cch++) {
        if (cch == NCH - 1) cp_wait0(); else cp_wait1();
        __syncthreads();
        if (cch + 2 < NCH) load_stage((cch + 2) % 3, cch + 2);
        compute_stage(cch % 3);
    }

    #pragma unroll
    for (int mi = 0; mi < 2; mi++)
        #pragma unroll
        for (int ni = 0; ni < 4; ni++) {
            int r  = m0 + mwb + mi * 16 + (lane >> 2);
            int cc = n0 + nwb + ni * 8 + 2 * (lane & 3);
            float bx = bias[cc], by = bias[cc + 1];
            size_t o0 = (size_t)r * H_DIM + cc;
            size_t o1 = o0 + (size_t)8 * H_DIM;
            *(float2*)(g_xproj + o0) = make_float2(c[mi][ni][0] + bx, c[mi][ni][1] + by);
            *(float2*)(g_xproj + o1) = make_float2(c[mi][ni][2] + bx, c[mi][ni][3] + by);
        }
}

// ---------------------------------------------------------------------------
// Persistent scan kernel: all 256 steps in ONE launch.
// Grid (64, 2) = 128 CTAs, 128 threads (4 warps, 2m x 2n).
// W_hi^T (fp16) resident in SMEM; h (fp16) + W_lo streamed via 3-stage
// cp.async pipeline; register double-buffered ldsm/mma; xproj prefetched;
// per-mh (64-CTA) release/acquire grid barrier each step.
// ---------------------------------------------------------------------------
__global__ __launch_bounds__(128) void scan_kernel(float* __restrict__ final_out) {
    extern __shared__ char smem[];
    const uint32_t sb = smem_u32(smem);
    const int tid = threadIdx.x, wid = tid >> 5, lane = tid & 31;
    const int nt = blockIdx.x, mh = blockIdx.y;
    const int n0 = nt * 32;
    const int m0 = mh * 64;

    // ---- load resident W_hi^T slice (32 rows x 2048 k), pitch 4112 ----
    {
        const __half* WHg = g_wr_hi + (size_t)n0 * H_DIM;
        #pragma unroll 4
        for (int idx = tid; idx < 32 * 256; idx += 128) {      // 16B units
            int r = idx >> 8, kc = idx & 255;
            cp16(sb + r * WPITCH + kc * 16, WHg + (size_t)r * H_DIM + kc * 8);
        }
        cp_commit();
        cp_wait0();
        __syncthreads();
    }

    const __half* __restrict__ WLg = g_wr_lo + (size_t)n0 * H_DIM;

    const int wm = wid >> 1, wn = wid & 1;
    const uint32_t aOff   = (uint32_t)((lane & 15) * ROWB + (lane >> 4) * 16);
    const uint32_t rowsel = (uint32_t)((lane & 7) | ((lane >> 1) & 8));
    const uint32_t bOffL  = rowsel * ROWB   + (lane & 8) * 2 + (uint32_t)(wn * 16) * ROWB;
    const uint32_t bOffH  = rowsel * WPITCH + (lane & 8) * 2 + (uint32_t)(wn * 16) * WPITCH;

    const int er  = m0 + wm * 32 + (lane >> 2);
    const int ecc = n0 + wn * 16 + 2 * (lane & 3);

    for (int t = 0; t < T_STEPS; t++) {
        const __half* __restrict__ Ahg = g_h[t & 1] + (size_t)m0 * H_DIM;
        const float* __restrict__ xp = g_xproj + (size_t)t * B_DIM * H_DIM;

        // ---- prefetch xproj fragment into registers ----
        float2 xf[2][2][2];
        #pragma unroll
        for (int mi = 0; mi < 2; mi++)
            #pragma unroll
            for (int ni = 0; ni < 2; ni++) {
                size_t o0 = (size_t)(er + mi * 16) * H_DIM + ecc + ni * 8;
                xf[mi][ni][0] = __ldg((const float2*)(xp + o0));
                xf[mi][ni][1] = __ldg((const float2*)(xp + o0 + (size_t)8 * H_DIM));
            }

        float c[2][2][4];
        #pragma unroll
        for (int i = 0; i < 2; i++)
            #pragma unroll
            for (int j = 0; j < 2; j++)
                #pragma unroll
                for (int q = 0; q < 4; q++) c[i][j][q] = 0.0f;

        auto load_stage = [&](int s, int cch) {
            const int k0 = cch * KC;
            uint32_t base = sb + WH_SZ + s * ST_SZ;
            #pragma unroll
            for (int j = 0; j < 4; j++) {          // h: 64 rows x 8 chunks
                int idx = tid + j * 128;
                int r = idx >> 3, kc = idx & 7;
                cp16(base + ST_A + r * ROWB + kc * 16,
                     Ahg + (size_t)r * H_DIM + k0 + kc * 8);
            }
            #pragma unroll
            for (int j = 0; j < 2; j++) {          // W_lo: 32 rows x 8 chunks
                int idx = tid + j * 128;
                int r = idx >> 3, kc = idx & 7;
                cp16(base + ST_WL + r * ROWB + kc * 16,
                     WLg + (size_t)r * H_DIM + k0 + kc * 8);
            }
            cp_commit();
        };

        auto compute_stage = [&](int s, int cch) {
            uint32_t base = sb + WH_SZ + s * ST_SZ;
            uint32_t aA = base + ST_A + (uint32_t)(wm * 32) * ROWB + aOff;
            uint32_t bL = base + ST_WL + bOffL;
            uint32_t bH = sb + bOffH + (uint32_t)(cch * KC) * 2;
            uint32_t ah[2][2][4], bh[2][4], bl[2][4];
            ldsm4(aA, ah[0][0]);
            ldsm4(aA + 16 * ROWB, ah[0][1]);
            ldsm4(bH, bh[0]);
            ldsm4(bL, bl[0]);
            #pragma unroll
            for (int kk = 0; kk < KC / 16; kk++) {
                int cur = kk & 1, nxt = cur ^ 1;
                if (kk + 1 < KC / 16) {            // prefetch next k16 fragments
                    ldsm4(aA + (kk + 1) * 32, ah[nxt][0]);
                    ldsm4(aA + 16 * ROWB + (kk + 1) * 32, ah[nxt][1]);
                    ldsm4(bH + (kk + 1) * 32, bh[nxt]);
                    ldsm4(bL + (kk + 1) * 32, bl[nxt]);
                }
                #pragma unroll
                for (int mi = 0; mi < 2; mi++)
                    #pragma unroll
                    for (int ni = 0; ni < 2; ni++) {
                        mma16816(c[mi][ni], ah[cur][mi], bh[cur][2 * ni], bh[cur][2 * ni + 1]);
                        mma16816(c[mi][ni], ah[cur][mi], bl[cur][2 * ni], bl[cur][2 * ni + 1]);
                    }
            }
        };

        // ---- 3-stage pipeline, one sync per chunk ----
        load_stage(0, 0);
        load_stage(1, 1);
        #pragma unroll 1
        for (int cch = 0; cch < NCH; cch++) {
            if (cch == NCH - 1) cp_wait0(); else cp_wait1();
            __syncthreads();
            if (cch + 2 < NCH) load_stage((cch + 2) % 3, cch + 2);
            compute_stage(cch % 3, cch);
        }

        // ---- epilogue: tanh(acc + xproj_t) -> h fp16 (or final fp32) ----
        const bool last = (t == T_STEPS - 1);
        __half* __restrict__ Hn = g_h[(t + 1) & 1];

        #pragma unroll
        for (int mi = 0; mi < 2; mi++)
            #pragma unroll
            for (int ni = 0; ni < 2; ni++) {
                size_t o0 = (size_t)(er + mi * 16) * H_DIM + ecc + ni * 8;
                size_t o1 = o0 + (size_t)8 * H_DIM;
                float2 x0 = xf[mi][ni][0];
                float2 x1 = xf[mi][ni][1];
                float v00 = fast_tanh(c[mi][ni][0] + x0.x);
                float v01 = fast_tanh(c[mi][ni][1] + x0.y);
                float v10 = fast_tanh(c[mi][ni][2] + x1.x);
                float v11 = fast_tanh(c[mi][ni][3] + x1.y);
                if (last) {
                    *(float2*)(final_out + o0) = make_float2(v00, v01);
                    *(float2*)(final_out + o1) = make_float2(v10, v11);
                } else {
                    *(__half2*)(Hn + o0) = __floats2half2_rn(v00, v01);
                    *(__half2*)(Hn + o1) = __floats2half2_rn(v10, v11);
                }
            }

        // ---- per-mh grid barrier (64 CTAs), release/acquire ----
        if (!last) {
            __syncthreads();
            if (tid == 0) {
                unsigned* bp = &g_bar[2 * t + mh];
                asm volatile("red.release.gpu.global.add.u32 [%0], %1;"
                             :: "l"(bp), "r"(1u) : "memory");
                unsigned v;
                do {
                    asm volatile("ld.acquire.gpu.global.u32 %0, [%1];"
                                 : "=r"(v) : "l"(bp) : "memory");
                } while (v < 64u);
            }
            __syncthreads();
        }
    }
}

// ---------------------------------------------------------------------------
// Host launch — plain kernel launches only, graph-capturable
// ---------------------------------------------------------------------------
extern "C" void kernel_launch(void* const* d_in, const int* in_sizes, int n_in,
                              void* d_out, int out_size)
{
    const float* x     = (const float*)d_in[0];
    const float* w_in  = (const float*)d_in[1];
    const float* w_rec = (const float*)d_in[2];
    const float* bias  = (const float*)d_in[3];
    float* out = (float*)d_out;

    void *p_wr_h, *p_wr_l, *p_wi_h, *p_wi_l;
    cudaGetSymbolAddress(&p_wr_h, g_wr_hi);
    cudaGetSymbolAddress(&p_wr_l, g_wr_lo);
    cudaGetSymbolAddress(&p_wi_h, g_wi_hi);
    cudaGetSymbolAddress(&p_wi_l, g_wi_lo);

    cudaFuncSetAttribute(scan_kernel,
                         cudaFuncAttributeMaxDynamicSharedMemorySize, SMEM_SCAN);
    cudaFuncSetAttribute(xproj_mma_kernel,
                         cudaFuncAttributeMaxDynamicSharedMemorySize, SMEM_XPROJ);

    // prep
    init_h0_kernel<<<(B_DIM * H_DIM + 255) / 256, 256>>>();
    conv_x_kernel<<<(int)(((size_t)T_STEPS * B_DIM * H_DIM) / 8 / 256), 256>>>(x);
    wsplit_kernel<<<dim3(H_DIM / 32, H_DIM / 32), dim3(32, 8)>>>(
        w_rec, (__half*)p_wr_h, (__half*)p_wr_l);
    wsplit_kernel<<<dim3(H_DIM / 32, H_DIM / 32), dim3(32, 8)>>>(
        w_in, (__half*)p_wi_h, (__half*)p_wi_l);

    // xproj (tensor-core, 2-product fp16)
    xproj_mma_kernel<<<dim3(H_DIM / 64, (T_STEPS * B_DIM) / 128), 256, SMEM_XPROJ>>>(bias);

    // persistent scan: all 256 steps in one launch
    scan_kernel<<<dim3(H_DIM / 32, B_DIM / 64), 128, SMEM_SCAN>>>(out);
}

// round 7
// speedup vs baseline: 6.9921x; 1.4342x over previous
#include <cuda_runtime.h>
#include <cuda_fp16.h>
#include <math.h>
#include <stdint.h>

#define T_STEPS 256
#define B_DIM   128
#define H_DIM   2048

// ---- xproj tiling (KC=64) ----
#define KC      64
#define NCH     (H_DIM / KC)       // 32
#define ROWB    144                // 64 fp16 + 16B pad

// ---- scan tiling (KC2=128) ----
#define KC2     128
#define NCH2    (H_DIM / KC2)      // 16
#define ROWB2   272                // 128 fp16 + 16B pad

// ---- persistent scan kernel smem ----
#define WPITCH   4112              // 2048*2 + 16 pad: conflict-free ldsm rows
#define WH_SZ    (32 * WPITCH)     // 131584 B resident W^T slice (fp16)
#define ST_SZ    (64 * ROWB2)      // 17408 B per h stage
#define SMEM_SCAN (WH_SZ + 3 * ST_SZ)   // 183808 (3-stage)

// ---- xproj kernel smem ----
#define X_A   0                    // x tile (fp16): 128*144 = 18432
#define X_BH  18432                // W_in hi: 64*144 = 9216
#define X_BL  27648                // W_in lo: 9216
#define X_STG 36864
#define SMEM_XPROJ (3 * X_STG)     // 110592

// ---------------------------------------------------------------------------
// Device scratch (no allocations allowed anywhere)
// ---------------------------------------------------------------------------
__device__ __align__(128) float  g_xproj[(size_t)T_STEPS * B_DIM * H_DIM];  // 256 MB
__device__ __align__(128) __half g_h[2][B_DIM * H_DIM];                     // fp16 hidden
__device__ __align__(128) __half g_wr[(size_t)H_DIM * H_DIM];               // w_rec^T fp16
__device__ __align__(128) __half g_wi_hi[(size_t)H_DIM * H_DIM];            // w_in^T splits
__device__ __align__(128) __half g_wi_lo[(size_t)H_DIM * H_DIM];
__device__ __align__(128) __half g_x[(size_t)T_STEPS * B_DIM * H_DIM];      // x fp16
__device__ unsigned g_bar[2 * T_STEPS];                                     // per-(t, mh) counters

// ---------------------------------------------------------------------------
// PTX helpers — legal on plain sm_103 target
// ---------------------------------------------------------------------------
__device__ __forceinline__ uint32_t smem_u32(const void* p) {
    uint32_t a;
    asm("{ .reg .u64 t; cvta.to.shared.u64 t, %1; cvt.u32.u64 %0, t; }"
        : "=r"(a) : "l"(p));
    return a;
}
__device__ __forceinline__ void cp16(uint32_t dst, const void* src) {
    asm volatile("cp.async.cg.shared.global [%0], [%1], 16;"
                 :: "r"(dst), "l"(src) : "memory");
}
__device__ __forceinline__ void cp_commit() {
    asm volatile("cp.async.commit_group;" ::: "memory");
}
__device__ __forceinline__ void cp_wait1() {
    asm volatile("cp.async.wait_group 1;" ::: "memory");
}
__device__ __forceinline__ void cp_wait0() {
    asm volatile("cp.async.wait_group 0;" ::: "memory");
}
__device__ __forceinline__ void ldsm4(uint32_t addr, uint32_t r[4]) {
    asm volatile("ldmatrix.sync.aligned.m8n8.x4.shared.b16 {%0,%1,%2,%3}, [%4];"
                 : "=r"(r[0]), "=r"(r[1]), "=r"(r[2]), "=r"(r[3]) : "r"(addr));
}
__device__ __forceinline__ void mma16816(float c[4], const uint32_t a[4],
                                         uint32_t b0, uint32_t b1) {
    asm volatile("mma.sync.aligned.m16n8k16.row.col.f32.f16.f16.f32 "
                 "{%0,%1,%2,%3},{%4,%5,%6,%7},{%8,%9},{%0,%1,%2,%3};"
                 : "+f"(c[0]), "+f"(c[1]), "+f"(c[2]), "+f"(c[3])
                 : "r"(a[0]), "r"(a[1]), "r"(a[2]), "r"(a[3]), "r"(b0), "r"(b1));
}

// ---------------------------------------------------------------------------
// FMA-only accurate tanh, |err| ~2e-7
// ---------------------------------------------------------------------------
__device__ __forceinline__ float fast_tanh(float x) {
    float ax = fminf(fabsf(x), 9.0f);
    float t  = ax * 2.8853900817779268f;
    float f  = t + 12582912.0f;
    int   n  = __float_as_int(f) - 0x4B400000;
    float r  = t - (f - 12582912.0f);
    float p = 1.5403530e-4f;
    p = fmaf(p, r, 1.3333558e-3f);
    p = fmaf(p, r, 9.6181291e-3f);
    p = fmaf(p, r, 5.5504109e-2f);
    p = fmaf(p, r, 2.4022651e-1f);
    p = fmaf(p, r, 6.9314718e-1f);
    p = fmaf(p, r, 1.0f);
    float e2x = p * __int_as_float((n + 127) << 23);
    float d = e2x + 1.0f;
    float rc = __int_as_float(0x7EF311C3 - __float_as_int(d));
    rc = rc * fmaf(-d, rc, 2.0f);
    rc = rc * fmaf(-d, rc, 2.0f);
    rc = rc * fmaf(-d, rc, 2.0f);
    float y = fmaf(-2.0f, rc, 1.0f);
    return __int_as_float(__float_as_int(y) | (__float_as_int(x) & 0x80000000));
}

// ---------------------------------------------------------------------------
// Prep kernels
// ---------------------------------------------------------------------------
__global__ void init_h0_kernel() {
    int i = blockIdx.x * blockDim.x + threadIdx.x;
    if (i < B_DIM * H_DIM) g_h[0][i] = __float2half(0.0f);
    if (i < 2 * T_STEPS) g_bar[i] = 0u;
}

// x (fp32) -> fp16, 8 elems per thread
__global__ __launch_bounds__(256) void conv_x_kernel(const float* __restrict__ x) {
    size_t i = ((size_t)blockIdx.x * blockDim.x + threadIdx.x) * 8;
    float4 v0 = *(const float4*)(x + i);
    float4 v1 = *(const float4*)(x + i + 4);
    __half2 h0 = __floats2half2_rn(v0.x, v0.y);
    __half2 h1 = __floats2half2_rn(v0.z, v0.w);
    __half2 h2 = __floats2half2_rn(v1.x, v1.y);
    __half2 h3 = __floats2half2_rn(v1.z, v1.w);
    *(uint4*)(g_x + i) = make_uint4(
        *(uint32_t*)&h0, *(uint32_t*)&h1, *(uint32_t*)&h2, *(uint32_t*)&h3);
}

// W (k,n) fp32 -> W^T (n,k) fp16 hi/lo splits (for w_in). 32x32 tiles.
__global__ __launch_bounds__(256) void wsplit_kernel(
    const float* __restrict__ W, __half* __restrict__ dh, __half* __restrict__ dl)
{
    __shared__ float tile[32][33];
    int tx = threadIdx.x, ty = threadIdx.y;
    int k0 = blockIdx.y * 32;
    int n0 = blockIdx.x * 32;
    #pragma unroll
    for (int j = 0; j < 32; j += 8)
        tile[ty + j][tx] = W[(size_t)(k0 + ty + j) * H_DIM + n0 + tx];
    __syncthreads();
    #pragma unroll
    for (int j = 0; j < 32; j += 8) {
        float v = tile[tx][ty + j];
        __half hi = __float2half(v);
        __half lo = __float2half(v - __half2float(hi));
        size_t idx = (size_t)(n0 + ty + j) * H_DIM + k0 + tx;
        dh[idx] = hi;
        dl[idx] = lo;
    }
}

// W (k,n) fp32 -> W^T (n,k) single fp16 (for w_rec). 32x32 tiles.
__global__ __launch_bounds__(256) void wtrans_kernel(
    const float* __restrict__ W, __half* __restrict__ d)
{
    __shared__ float tile[32][33];
    int tx = threadIdx.x, ty = threadIdx.y;
    int k0 = blockIdx.y * 32;
    int n0 = blockIdx.x * 32;
    #pragma unroll
    for (int j = 0; j < 32; j += 8)
        tile[ty + j][tx] = W[(size_t)(k0 + ty + j) * H_DIM + n0 + tx];
    __syncthreads();
    #pragma unroll
    for (int j = 0; j < 32; j += 8) {
        size_t idx = (size_t)(n0 + ty + j) * H_DIM + k0 + tx;
        d[idx] = __float2half(tile[tx][ty + j]);
    }
}

// ---------------------------------------------------------------------------
// xproj = X @ W_in + bias  (fp16 2-product HMMA, 3-stage pipeline)
// CTA tile 128x64, 8 warps (4m x 2n), warp tile 32x32. Grid (32, 256).
// ---------------------------------------------------------------------------
__global__ __launch_bounds__(256) void xproj_mma_kernel(const float* __restrict__ bias) {
    extern __shared__ char smem[];
    const uint32_t sb = smem_u32(smem);
    const int tid = threadIdx.x, wid = tid >> 5, lane = tid & 31;
    const int m0 = blockIdx.y * 128;
    const int n0 = blockIdx.x * 64;

    const __half* __restrict__ A  = g_x + (size_t)m0 * H_DIM;
    const __half* __restrict__ Bh = g_wi_hi + (size_t)n0 * H_DIM;
    const __half* __restrict__ Bl = g_wi_lo + (size_t)n0 * H_DIM;

    float c[2][4][4];
    #pragma unroll
    for (int i = 0; i < 2; i++)
        #pragma unroll
        for (int j = 0; j < 4; j++)
            #pragma unroll
            for (int q = 0; q < 4; q++) c[i][j][q] = 0.0f;

    auto load_stage = [&](int s, int cch) {
        const int k0 = cch * KC;
        uint32_t base = sb + s * X_STG;
        #pragma unroll
        for (int j = 0; j < 4; j++) {              // A: 128 rows x 8 chunks
            int idx = tid + j * 256;
            int r = idx >> 3, kc = idx & 7;
            cp16(base + X_A + r * ROWB + kc * 16, A + (size_t)r * H_DIM + k0 + kc * 8);
        }
        #pragma unroll
        for (int j = 0; j < 2; j++) {              // B hi+lo: 64 rows x 8 chunks
            int idx = tid + j * 256;
            int r = idx >> 3, kc = idx & 7;
            size_t go = (size_t)r * H_DIM + k0 + kc * 8;
            cp16(base + X_BH + r * ROWB + kc * 16, Bh + go);
            cp16(base + X_BL + r * ROWB + kc * 16, Bl + go);
        }
        cp_commit();
    };

    const int mwb = (wid >> 1) * 32;
    const int nwb = (wid & 1) * 32;
    const uint32_t aOff = (uint32_t)((lane & 15) * ROWB + (lane >> 4) * 16);
    const uint32_t bOff = (uint32_t)(((lane & 7) | ((lane >> 1) & 8)) * ROWB + (lane & 8) * 2);

    auto compute_stage = [&](int s) {
        uint32_t base = sb + s * X_STG;
        uint32_t aA = base + X_A  + mwb * ROWB + aOff;
        uint32_t bH = base + X_BH + nwb * ROWB + bOff;
        uint32_t bL = base + X_BL + nwb * ROWB + bOff;
        uint32_t ah[2][2][4], bh[2][8], bl[2][8];
        ldsm4(aA, ah[0][0]);
        ldsm4(aA + 16 * ROWB, ah[0][1]);
        ldsm4(bH, bh[0]);
        ldsm4(bH + 16 * ROWB, bh[0] + 4);
        ldsm4(bL, bl[0]);
        ldsm4(bL + 16 * ROWB, bl[0] + 4);
        #pragma unroll
        for (int kk = 0; kk < KC / 16; kk++) {
            int cur = kk & 1, nxt = cur ^ 1;
            if (kk + 1 < KC / 16) {                // prefetch next k16 fragments
                ldsm4(aA + (kk + 1) * 32, ah[nxt][0]);
                ldsm4(aA + 16 * ROWB + (kk + 1) * 32, ah[nxt][1]);
                ldsm4(bH + (kk + 1) * 32, bh[nxt]);
                ldsm4(bH + 16 * ROWB + (kk + 1) * 32, bh[nxt] + 4);
                ldsm4(bL + (kk + 1) * 32, bl[nxt]);
                ldsm4(bL + 16 * ROWB + (kk + 1) * 32, bl[nxt] + 4);
            }
            #pragma unroll
            for (int mi = 0; mi < 2; mi++)
                #pragma unroll
                for (int ni = 0; ni < 4; ni++) {
                    mma16816(c[mi][ni], ah[cur][mi], bh[cur][2 * ni], bh[cur][2 * ni + 1]);
                    mma16816(c[mi][ni], ah[cur][mi], bl[cur][2 * ni], bl[cur][2 * ni + 1]);
                }
        }
    };

    load_stage(0, 0);
    load_stage(1, 1);
    #pragma unroll 1
    for (int cch = 0; cch < NCH; cch++) {
        if (cch == NCH - 1) cp_wait0(); else cp_wait1();
        __syncthreads();
        if (cch + 2 < NCH) load_stage((cch + 2) % 3, cch + 2);
        compute_stage(cch % 3);
    }

    #pragma unroll
    for (int mi = 0; mi < 2; mi++)
        #pragma unroll
        for (int ni = 0; ni < 4; ni++) {
            int r  = m0 + mwb + mi * 16 + (lane >> 2);
            int cc = n0 + nwb + ni * 8 + 2 * (lane & 3);
            float bx = bias[cc], by = bias[cc + 1];
            size_t o0 = (size_t)r * H_DIM + cc;
            size_t o1 = o0 + (size_t)8 * H_DIM;
            *(float2*)(g_xproj + o0) = make_float2(c[mi][ni][0] + bx, c[mi][ni][1] + by);
            *(float2*)(g_xproj + o1) = make_float2(c[mi][ni][2] + bx, c[mi][ni][3] + by);
        }
}

// ---------------------------------------------------------------------------
// Persistent scan kernel: all 256 steps in ONE launch.
// Grid (64, 2) = 128 CTAs, 128 threads (4 warps, 2m x 2n).
// W^T slice (fp16, single) resident in SMEM; only h streamed via 3-stage
// cp.async pipeline (KC2=128 -> 16 chunks, 16 syncs/step); register
// double-buffered ldsm/mma; xproj prefetched; per-mh 64-CTA barrier.
// ---------------------------------------------------------------------------
__global__ __launch_bounds__(128) void scan_kernel(float* __restrict__ final_out) {
    extern __shared__ char smem[];
    const uint32_t sb = smem_u32(smem);
    const int tid = threadIdx.x, wid = tid >> 5, lane = tid & 31;
    const int nt = blockIdx.x, mh = blockIdx.y;
    const int n0 = nt * 32;
    const int m0 = mh * 64;

    // ---- load resident W^T slice (32 rows x 2048 k), pitch 4112 ----
    {
        const __half* Wg = g_wr + (size_t)n0 * H_DIM;
        #pragma unroll 4
        for (int idx = tid; idx < 32 * 256; idx += 128) {      // 16B units
            int r = idx >> 8, kc = idx & 255;
            cp16(sb + r * WPITCH + kc * 16, Wg + (size_t)r * H_DIM + kc * 8);
        }
        cp_commit();
        cp_wait0();
        __syncthreads();
    }

    const int wm = wid >> 1, wn = wid & 1;
    const uint32_t aOff   = (uint32_t)((lane & 15) * ROWB2 + (lane >> 4) * 16);
    const uint32_t rowsel = (uint32_t)((lane & 7) | ((lane >> 1) & 8));
    const uint32_t bOffH  = rowsel * WPITCH + (lane & 8) * 2 + (uint32_t)(wn * 16) * WPITCH;

    const int er  = m0 + wm * 32 + (lane >> 2);
    const int ecc = n0 + wn * 16 + 2 * (lane & 3);

    for (int t = 0; t < T_STEPS; t++) {
        const __half* __restrict__ Ahg = g_h[t & 1] + (size_t)m0 * H_DIM;
        const float* __restrict__ xp = g_xproj + (size_t)t * B_DIM * H_DIM;

        // ---- prefetch xproj fragment into registers ----
        float2 xf[2][2][2];
        #pragma unroll
        for (int mi = 0; mi < 2; mi++)
            #pragma unroll
            for (int ni = 0; ni < 2; ni++) {
                size_t o0 = (size_t)(er + mi * 16) * H_DIM + ecc + ni * 8;
                xf[mi][ni][0] = __ldg((const float2*)(xp + o0));
                xf[mi][ni][1] = __ldg((const float2*)(xp + o0 + (size_t)8 * H_DIM));
            }

        float c[2][2][4];
        #pragma unroll
        for (int i = 0; i < 2; i++)
            #pragma unroll
            for (int j = 0; j < 2; j++)
                #pragma unroll
                for (int q = 0; q < 4; q++) c[i][j][q] = 0.0f;

        auto load_stage = [&](int s, int cch) {
            const int k0 = cch * KC2;
            uint32_t base = sb + WH_SZ + s * ST_SZ;
            #pragma unroll
            for (int j = 0; j < 8; j++) {          // h: 64 rows x 16 chunks of 16B
                int idx = tid + j * 128;
                int r = idx >> 4, kc = idx & 15;
                cp16(base + r * ROWB2 + kc * 16,
                     Ahg + (size_t)r * H_DIM + k0 + kc * 8);
            }
            cp_commit();
        };

        auto compute_stage = [&](int s, int cch) {
            uint32_t base = sb + WH_SZ + s * ST_SZ;
            uint32_t aA = base + (uint32_t)(wm * 32) * ROWB2 + aOff;
            uint32_t bH = sb + bOffH + (uint32_t)(cch * KC2) * 2;
            uint32_t ah[2][2][4], bh[2][4];
            ldsm4(aA, ah[0][0]);
            ldsm4(aA + 16 * ROWB2, ah[0][1]);
            ldsm4(bH, bh[0]);
            #pragma unroll
            for (int kk = 0; kk < KC2 / 16; kk++) {
                int cur = kk & 1, nxt = cur ^ 1;
                if (kk + 1 < KC2 / 16) {           // prefetch next k16 fragments
                    ldsm4(aA + (kk + 1) * 32, ah[nxt][0]);
                    ldsm4(aA + 16 * ROWB2 + (kk + 1) * 32, ah[nxt][1]);
                    ldsm4(bH + (kk + 1) * 32, bh[nxt]);
                }
                #pragma unroll
                for (int mi = 0; mi < 2; mi++)
                    #pragma unroll
                    for (int ni = 0; ni < 2; ni++)
                        mma16816(c[mi][ni], ah[cur][mi], bh[cur][2 * ni], bh[cur][2 * ni + 1]);
            }
        };

        // ---- 3-stage pipeline, one sync per chunk ----
        load_stage(0, 0);
        load_stage(1, 1);
        #pragma unroll 1
        for (int cch = 0; cch < NCH2; cch++) {
            if (cch == NCH2 - 1) cp_wait0(); else cp_wait1();
            __syncthreads();
            if (cch + 2 < NCH2) load_stage((cch + 2) % 3, cch + 2);
            compute_stage(cch % 3, cch);
        }

        // ---- epilogue: tanh(acc + xproj_t) -> h fp16 (or final fp32) ----
        const bool last = (t == T_STEPS - 1);
        __half* __restrict__ Hn = g_h[(t + 1) & 1];

        #pragma unroll
        for (int mi = 0; mi < 2; mi++)
            #pragma unroll
            for (int ni = 0; ni < 2; ni++) {
                size_t o0 = (size_t)(er + mi * 16) * H_DIM + ecc + ni * 8;
                size_t o1 = o0 + (size_t)8 * H_DIM;
                float2 x0 = xf[mi][ni][0];
                float2 x1 = xf[mi][ni][1];
                float v00 = fast_tanh(c[mi][ni][0] + x0.x);
                float v01 = fast_tanh(c[mi][ni][1] + x0.y);
                float v10 = fast_tanh(c[mi][ni][2] + x1.x);
                float v11 = fast_tanh(c[mi][ni][3] + x1.y);
                if (last) {
                    *(float2*)(final_out + o0) = make_float2(v00, v01);
                    *(float2*)(final_out + o1) = make_float2(v10, v11);
                } else {
                    *(__half2*)(Hn + o0) = __floats2half2_rn(v00, v01);
                    *(__half2*)(Hn + o1) = __floats2half2_rn(v10, v11);
                }
            }

        // ---- per-mh grid barrier (64 CTAs), release/acquire ----
        if (!last) {
            __syncthreads();
            if (tid == 0) {
                unsigned* bp = &g_bar[2 * t + mh];
                asm volatile("red.release.gpu.global.add.u32 [%0], %1;"
                             :: "l"(bp), "r"(1u) : "memory");
                unsigned v;
                do {
                    asm volatile("ld.acquire.gpu.global.u32 %0, [%1];"
                                 : "=r"(v) : "l"(bp) : "memory");
                } while (v < 64u);
            }
            __syncthreads();
        }
    }
}

// ---------------------------------------------------------------------------
// Host launch — plain kernel launches only, graph-capturable
// ---------------------------------------------------------------------------
extern "C" void kernel_launch(void* const* d_in, const int* in_sizes, int n_in,
                              void* d_out, int out_size)
{
    const float* x     = (const float*)d_in[0];
    const float* w_in  = (const float*)d_in[1];
    const float* w_rec = (const float*)d_in[2];
    const float* bias  = (const float*)d_in[3];
    float* out = (float*)d_out;

    void *p_wr, *p_wi_h, *p_wi_l;
    cudaGetSymbolAddress(&p_wr, g_wr);
    cudaGetSymbolAddress(&p_wi_h, g_wi_hi);
    cudaGetSymbolAddress(&p_wi_l, g_wi_lo);

    cudaFuncSetAttribute(scan_kernel,
                         cudaFuncAttributeMaxDynamicSharedMemorySize, SMEM_SCAN);
    cudaFuncSetAttribute(xproj_mma_kernel,
                         cudaFuncAttributeMaxDynamicSharedMemorySize, SMEM_XPROJ);

    // prep
    init_h0_kernel<<<(B_DIM * H_DIM + 255) / 256, 256>>>();
    conv_x_kernel<<<(int)(((size_t)T_STEPS * B_DIM * H_DIM) / 8 / 256), 256>>>(x);
    wtrans_kernel<<<dim3(H_DIM / 32, H_DIM / 32), dim3(32, 8)>>>(
        w_rec, (__half*)p_wr);
    wsplit_kernel<<<dim3(H_DIM / 32, H_DIM / 32), dim3(32, 8)>>>(
        w_in, (__half*)p_wi_h, (__half*)p_wi_l);

    // xproj (tensor-core, 2-product fp16)
    xproj_mma_kernel<<<dim3(H_DIM / 64, (T_STEPS * B_DIM) / 128), 256, SMEM_XPROJ>>>(bias);

    // persistent scan: all 256 steps in one launch
    scan_kernel<<<dim3(H_DIM / 32, B_DIM / 64), 128, SMEM_SCAN>>>(out);
}

// round 8
// speedup vs baseline: 7.6339x; 1.0918x over previous
#include <cuda_runtime.h>
#include <cuda_fp16.h>
#include <math.h>
#include <stdint.h>

#define T_STEPS 256
#define B_DIM   128
#define H_DIM   2048

// ---- xproj tiling (KC=64) ----
#define KC      64
#define NCH     (H_DIM / KC)       // 32
#define ROWB    144                // 64 fp16 + 16B pad

// ---- scan tiling (KC2=128) ----
#define KC2     128
#define NCH2    (H_DIM / KC2)      // 16
#define ROWB2   272                // 128 fp16 + 16B pad

// ---- persistent scan kernel smem ----
#define WPITCH   4112              // 2048*2 + 16 pad: conflict-free ldsm rows
#define WH_SZ    (32 * WPITCH)     // 131584 B resident W^T slice (fp16)
#define ST_SZ    (64 * ROWB2)      // 17408 B per h stage
#define SMEM_SCAN (WH_SZ + 3 * ST_SZ)   // 183808 (3-stage)

// ---- xproj kernel smem (1-product: A + B_hi only) ----
#define X_A   0                    // x tile (fp16): 128*144 = 18432
#define X_B   18432                // W_in: 64*144 = 9216
#define X_STG 27648
#define SMEM_XPROJ (3 * X_STG)     // 82944

// ---------------------------------------------------------------------------
// Device scratch (no allocations allowed anywhere)
// ---------------------------------------------------------------------------
__device__ __align__(128) float  g_xproj[(size_t)T_STEPS * B_DIM * H_DIM];  // 256 MB
__device__ __align__(128) __half g_h[2][B_DIM * H_DIM];                     // fp16 hidden
__device__ __align__(128) __half g_wr[(size_t)H_DIM * H_DIM];               // w_rec^T fp16
__device__ __align__(128) __half g_wi[(size_t)H_DIM * H_DIM];               // w_in^T fp16
__device__ __align__(128) __half g_x[(size_t)T_STEPS * B_DIM * H_DIM];      // x fp16
__device__ unsigned g_bar[2 * T_STEPS];                                     // per-(t, mh) counters

// ---------------------------------------------------------------------------
// PTX helpers — legal on plain sm_103 target
// ---------------------------------------------------------------------------
__device__ __forceinline__ uint32_t smem_u32(const void* p) {
    uint32_t a;
    asm("{ .reg .u64 t; cvta.to.shared.u64 t, %1; cvt.u32.u64 %0, t; }"
        : "=r"(a) : "l"(p));
    return a;
}
__device__ __forceinline__ void cp16(uint32_t dst, const void* src) {
    asm volatile("cp.async.cg.shared.global [%0], [%1], 16;"
                 :: "r"(dst), "l"(src) : "memory");
}
__device__ __forceinline__ void cp_commit() {
    asm volatile("cp.async.commit_group;" ::: "memory");
}
__device__ __forceinline__ void cp_wait1() {
    asm volatile("cp.async.wait_group 1;" ::: "memory");
}
__device__ __forceinline__ void cp_wait0() {
    asm volatile("cp.async.wait_group 0;" ::: "memory");
}
__device__ __forceinline__ void ldsm4(uint32_t addr, uint32_t r[4]) {
    asm volatile("ldmatrix.sync.aligned.m8n8.x4.shared.b16 {%0,%1,%2,%3}, [%4];"
                 : "=r"(r[0]), "=r"(r[1]), "=r"(r[2]), "=r"(r[3]) : "r"(addr));
}
__device__ __forceinline__ void mma16816(float c[4], const uint32_t a[4],
                                         uint32_t b0, uint32_t b1) {
    asm volatile("mma.sync.aligned.m16n8k16.row.col.f32.f16.f16.f32 "
                 "{%0,%1,%2,%3},{%4,%5,%6,%7},{%8,%9},{%0,%1,%2,%3};"
                 : "+f"(c[0]), "+f"(c[1]), "+f"(c[2]), "+f"(c[3])
                 : "r"(a[0]), "r"(a[1]), "r"(a[2]), "r"(a[3]), "r"(b0), "r"(b1));
}

// ---------------------------------------------------------------------------
// FMA-only accurate tanh, |err| ~2e-7
// ---------------------------------------------------------------------------
__device__ __forceinline__ float fast_tanh(float x) {
    float ax = fminf(fabsf(x), 9.0f);
    float t  = ax * 2.8853900817779268f;
    float f  = t + 12582912.0f;
    int   n  = __float_as_int(f) - 0x4B400000;
    float r  = t - (f - 12582912.0f);
    float p = 1.5403530e-4f;
    p = fmaf(p, r, 1.3333558e-3f);
    p = fmaf(p, r, 9.6181291e-3f);
    p = fmaf(p, r, 5.5504109e-2f);
    p = fmaf(p, r, 2.4022651e-1f);
    p = fmaf(p, r, 6.9314718e-1f);
    p = fmaf(p, r, 1.0f);
    float e2x = p * __int_as_float((n + 127) << 23);
    float d = e2x + 1.0f;
    float rc = __int_as_float(0x7EF311C3 - __float_as_int(d));
    rc = rc * fmaf(-d, rc, 2.0f);
    rc = rc * fmaf(-d, rc, 2.0f);
    rc = rc * fmaf(-d, rc, 2.0f);
    float y = fmaf(-2.0f, rc, 1.0f);
    return __int_as_float(__float_as_int(y) | (__float_as_int(x) & 0x80000000));
}

// ---------------------------------------------------------------------------
// Prep kernels
// ---------------------------------------------------------------------------
__global__ void init_h0_kernel() {
    int i = blockIdx.x * blockDim.x + threadIdx.x;
    if (i < B_DIM * H_DIM) g_h[0][i] = __float2half(0.0f);
    if (i < 2 * T_STEPS) g_bar[i] = 0u;
}

// x (fp32) -> fp16, 8 elems per thread
__global__ __launch_bounds__(256) void conv_x_kernel(const float* __restrict__ x) {
    size_t i = ((size_t)blockIdx.x * blockDim.x + threadIdx.x) * 8;
    float4 v0 = *(const float4*)(x + i);
    float4 v1 = *(const float4*)(x + i + 4);
    __half2 h0 = __floats2half2_rn(v0.x, v0.y);
    __half2 h1 = __floats2half2_rn(v0.z, v0.w);
    __half2 h2 = __floats2half2_rn(v1.x, v1.y);
    __half2 h3 = __floats2half2_rn(v1.z, v1.w);
    *(uint4*)(g_x + i) = make_uint4(
        *(uint32_t*)&h0, *(uint32_t*)&h1, *(uint32_t*)&h2, *(uint32_t*)&h3);
}

// W (k,n) fp32 -> W^T (n,k) single fp16. 32x32 tiles.
__global__ __launch_bounds__(256) void wtrans_kernel(
    const float* __restrict__ W, __half* __restrict__ d)
{
    __shared__ float tile[32][33];
    int tx = threadIdx.x, ty = threadIdx.y;
    int k0 = blockIdx.y * 32;
    int n0 = blockIdx.x * 32;
    #pragma unroll
    for (int j = 0; j < 32; j += 8)
        tile[ty + j][tx] = W[(size_t)(k0 + ty + j) * H_DIM + n0 + tx];
    __syncthreads();
    #pragma unroll
    for (int j = 0; j < 32; j += 8) {
        size_t idx = (size_t)(n0 + ty + j) * H_DIM + k0 + tx;
        d[idx] = __float2half(tile[tx][ty + j]);
    }
}

// ---------------------------------------------------------------------------
// xproj = X @ W_in + bias  (fp16 1-product HMMA, 3-stage pipeline)
// CTA tile 128x64, 8 warps (4m x 2n), warp tile 32x32. Grid (32, 256).
// ---------------------------------------------------------------------------
__global__ __launch_bounds__(256) void xproj_mma_kernel(const float* __restrict__ bias) {
    extern __shared__ char smem[];
    const uint32_t sb = smem_u32(smem);
    const int tid = threadIdx.x, wid = tid >> 5, lane = tid & 31;
    const int m0 = blockIdx.y * 128;
    const int n0 = blockIdx.x * 64;

    const __half* __restrict__ A = g_x + (size_t)m0 * H_DIM;
    const __half* __restrict__ B = g_wi + (size_t)n0 * H_DIM;

    float c[2][4][4];
    #pragma unroll
    for (int i = 0; i < 2; i++)
        #pragma unroll
        for (int j = 0; j < 4; j++)
            #pragma unroll
            for (int q = 0; q < 4; q++) c[i][j][q] = 0.0f;

    auto load_stage = [&](int s, int cch) {
        const int k0 = cch * KC;
        uint32_t base = sb + s * X_STG;
        #pragma unroll
        for (int j = 0; j < 4; j++) {              // A: 128 rows x 8 chunks
            int idx = tid + j * 256;
            int r = idx >> 3, kc = idx & 7;
            cp16(base + X_A + r * ROWB + kc * 16, A + (size_t)r * H_DIM + k0 + kc * 8);
        }
        #pragma unroll
        for (int j = 0; j < 2; j++) {              // B: 64 rows x 8 chunks
            int idx = tid + j * 256;
            int r = idx >> 3, kc = idx & 7;
            cp16(base + X_B + r * ROWB + kc * 16, B + (size_t)r * H_DIM + k0 + kc * 8);
        }
        cp_commit();
    };

    const int mwb = (wid >> 1) * 32;
    const int nwb = (wid & 1) * 32;
    const uint32_t aOff = (uint32_t)((lane & 15) * ROWB + (lane >> 4) * 16);
    const uint32_t bOff = (uint32_t)(((lane & 7) | ((lane >> 1) & 8)) * ROWB + (lane & 8) * 2);

    auto compute_stage = [&](int s) {
        uint32_t base = sb + s * X_STG;
        uint32_t aA = base + X_A + mwb * ROWB + aOff;
        uint32_t bB = base + X_B + nwb * ROWB + bOff;
        uint32_t ah[2][2][4], bh[2][8];
        ldsm4(aA, ah[0][0]);
        ldsm4(aA + 16 * ROWB, ah[0][1]);
        ldsm4(bB, bh[0]);
        ldsm4(bB + 16 * ROWB, bh[0] + 4);
        #pragma unroll
        for (int kk = 0; kk < KC / 16; kk++) {
            int cur = kk & 1, nxt = cur ^ 1;
            if (kk + 1 < KC / 16) {                // prefetch next k16 fragments
                ldsm4(aA + (kk + 1) * 32, ah[nxt][0]);
                ldsm4(aA + 16 * ROWB + (kk + 1) * 32, ah[nxt][1]);
                ldsm4(bB + (kk + 1) * 32, bh[nxt]);
                ldsm4(bB + 16 * ROWB + (kk + 1) * 32, bh[nxt] + 4);
            }
            #pragma unroll
            for (int mi = 0; mi < 2; mi++)
                #pragma unroll
                for (int ni = 0; ni < 4; ni++)
                    mma16816(c[mi][ni], ah[cur][mi], bh[cur][2 * ni], bh[cur][2 * ni + 1]);
        }
    };

    load_stage(0, 0);
    load_stage(1, 1);
    #pragma unroll 1
    for (int cch = 0; cch < NCH; cch++) {
        if (cch == NCH - 1) cp_wait0(); else cp_wait1();
        __syncthreads();
        if (cch + 2 < NCH) load_stage((cch + 2) % 3, cch + 2);
        compute_stage(cch % 3);
    }

    #pragma unroll
    for (int mi = 0; mi < 2; mi++)
        #pragma unroll
        for (int ni = 0; ni < 4; ni++) {
            int r  = m0 + mwb + mi * 16 + (lane >> 2);
            int cc = n0 + nwb + ni * 8 + 2 * (lane & 3);
            float bx = bias[cc], by = bias[cc + 1];
            size_t o0 = (size_t)r * H_DIM + cc;
            size_t o1 = o0 + (size_t)8 * H_DIM;
            *(float2*)(g_xproj + o0) = make_float2(c[mi][ni][0] + bx, c[mi][ni][1] + by);
            *(float2*)(g_xproj + o1) = make_float2(c[mi][ni][2] + bx, c[mi][ni][3] + by);
        }
}

// ---------------------------------------------------------------------------
// Persistent scan kernel: all 256 steps in ONE launch.
// Grid (64, 2) = 128 CTAs, 256 threads (8 warps, 4m x 2n, warp tile 16x16)
// -> 2 warps/SMSP for latency hiding.
// W^T slice (fp16) resident in SMEM; h streamed via 3-stage cp.async
// pipeline (KC2=128); register double-buffered ldsm/mma; xproj prefetched;
// per-mh 64-CTA release/acquire barrier.
// ---------------------------------------------------------------------------
__global__ __launch_bounds__(256) void scan_kernel(float* __restrict__ final_out) {
    extern __shared__ char smem[];
    const uint32_t sb = smem_u32(smem);
    const int tid = threadIdx.x, wid = tid >> 5, lane = tid & 31;
    const int nt = blockIdx.x, mh = blockIdx.y;
    const int n0 = nt * 32;
    const int m0 = mh * 64;

    // ---- load resident W^T slice (32 rows x 2048 k), pitch 4112 ----
    {
        const __half* Wg = g_wr + (size_t)n0 * H_DIM;
        #pragma unroll 4
        for (int idx = tid; idx < 32 * 256; idx += 256) {      // 16B units
            int r = idx >> 8, kc = idx & 255;
            cp16(sb + r * WPITCH + kc * 16, Wg + (size_t)r * H_DIM + kc * 8);
        }
        cp_commit();
        cp_wait0();
        __syncthreads();
    }

    const int wm = wid >> 1, wn = wid & 1;                     // 4m x 2n warps
    const uint32_t aOff   = (uint32_t)((lane & 15) * ROWB2 + (lane >> 4) * 16);
    const uint32_t rowsel = (uint32_t)((lane & 7) | ((lane >> 1) & 8));
    const uint32_t bOffH  = rowsel * WPITCH + (lane & 8) * 2 + (uint32_t)(wn * 16) * WPITCH;

    const int er  = m0 + wm * 16 + (lane >> 2);
    const int ecc = n0 + wn * 16 + 2 * (lane & 3);

    for (int t = 0; t < T_STEPS; t++) {
        const __half* __restrict__ Ahg = g_h[t & 1] + (size_t)m0 * H_DIM;
        const float* __restrict__ xp = g_xproj + (size_t)t * B_DIM * H_DIM;

        // ---- prefetch xproj fragment into registers ----
        float2 xf[2][2];
        #pragma unroll
        for (int ni = 0; ni < 2; ni++) {
            size_t o0 = (size_t)er * H_DIM + ecc + ni * 8;
            xf[ni][0] = __ldg((const float2*)(xp + o0));
            xf[ni][1] = __ldg((const float2*)(xp + o0 + (size_t)8 * H_DIM));
        }

        float c[2][4];
        #pragma unroll
        for (int j = 0; j < 2; j++)
            #pragma unroll
            for (int q = 0; q < 4; q++) c[j][q] = 0.0f;

        auto load_stage = [&](int s, int cch) {
            const int k0 = cch * KC2;
            uint32_t base = sb + WH_SZ + s * ST_SZ;
            #pragma unroll
            for (int j = 0; j < 4; j++) {          // h: 64 rows x 16 chunks of 16B
                int idx = tid + j * 256;
                int r = idx >> 4, kc = idx & 15;
                cp16(base + r * ROWB2 + kc * 16,
                     Ahg + (size_t)r * H_DIM + k0 + kc * 8);
            }
            cp_commit();
        };

        auto compute_stage = [&](int s, int cch) {
            uint32_t base = sb + WH_SZ + s * ST_SZ;
            uint32_t aA = base + (uint32_t)(wm * 16) * ROWB2 + aOff;
            uint32_t bH = sb + bOffH + (uint32_t)(cch * KC2) * 2;
            uint32_t ah[2][4], bh[2][4];
            ldsm4(aA, ah[0]);
            ldsm4(bH, bh[0]);
            #pragma unroll
            for (int kk = 0; kk < KC2 / 16; kk++) {
                int cur = kk & 1, nxt = cur ^ 1;
                if (kk + 1 < KC2 / 16) {           // prefetch next k16 fragments
                    ldsm4(aA + (kk + 1) * 32, ah[nxt]);
                    ldsm4(bH + (kk + 1) * 32, bh[nxt]);
                }
                #pragma unroll
                for (int ni = 0; ni < 2; ni++)
                    mma16816(c[ni], ah[cur], bh[cur][2 * ni], bh[cur][2 * ni + 1]);
            }
        };

        // ---- 3-stage pipeline, one sync per chunk ----
        load_stage(0, 0);
        load_stage(1, 1);
        #pragma unroll 1
        for (int cch = 0; cch < NCH2; cch++) {
            if (cch == NCH2 - 1) cp_wait0(); else cp_wait1();
            __syncthreads();
            if (cch + 2 < NCH2) load_stage((cch + 2) % 3, cch + 2);
            compute_stage(cch % 3, cch);
        }

        // ---- epilogue: tanh(acc + xproj_t) -> h fp16 (or final fp32) ----
        const bool last = (t == T_STEPS - 1);
        __half* __restrict__ Hn = g_h[(t + 1) & 1];

        #pragma unroll
        for (int ni = 0; ni < 2; ni++) {
            size_t o0 = (size_t)er * H_DIM + ecc + ni * 8;
            size_t o1 = o0 + (size_t)8 * H_DIM;
            float2 x0 = xf[ni][0];
            float2 x1 = xf[ni][1];
            float v00 = fast_tanh(c[ni][0] + x0.x);
            float v01 = fast_tanh(c[ni][1] + x0.y);
            float v10 = fast_tanh(c[ni][2] + x1.x);
            float v11 = fast_tanh(c[ni][3] + x1.y);
            if (last) {
                *(float2*)(final_out + o0) = make_float2(v00, v01);
                *(float2*)(final_out + o1) = make_float2(v10, v11);
            } else {
                *(__half2*)(Hn + o0) = __floats2half2_rn(v00, v01);
                *(__half2*)(Hn + o1) = __floats2half2_rn(v10, v11);
            }
        }

        // ---- per-mh grid barrier (64 CTAs), release/acquire ----
        if (!last) {
            __syncthreads();
            if (tid == 0) {
                unsigned* bp = &g_bar[2 * t + mh];
                asm volatile("red.release.gpu.global.add.u32 [%0], %1;"
                             :: "l"(bp), "r"(1u) : "memory");
                unsigned v;
                do {
                    asm volatile("ld.acquire.gpu.global.u32 %0, [%1];"
                                 : "=r"(v) : "l"(bp) : "memory");
                } while (v < 64u);
            }
            __syncthreads();
        }
    }
}

// ---------------------------------------------------------------------------
// Host launch — plain kernel launches only, graph-capturable
// ---------------------------------------------------------------------------
extern "C" void kernel_launch(void* const* d_in, const int* in_sizes, int n_in,
                              void* d_out, int out_size)
{
    const float* x     = (const float*)d_in[0];
    const float* w_in  = (const float*)d_in[1];
    const float* w_rec = (const float*)d_in[2];
    const float* bias  = (const float*)d_in[3];
    float* out = (float*)d_out;

    void *p_wr, *p_wi;
    cudaGetSymbolAddress(&p_wr, g_wr);
    cudaGetSymbolAddress(&p_wi, g_wi);

    cudaFuncSetAttribute(scan_kernel,
                         cudaFuncAttributeMaxDynamicSharedMemorySize, SMEM_SCAN);
    cudaFuncSetAttribute(xproj_mma_kernel,
                         cudaFuncAttributeMaxDynamicSharedMemorySize, SMEM_XPROJ);

    // prep
    init_h0_kernel<<<(B_DIM * H_DIM + 255) / 256, 256>>>();
    conv_x_kernel<<<(int)(((size_t)T_STEPS * B_DIM * H_DIM) / 8 / 256), 256>>>(x);
    wtrans_kernel<<<dim3(H_DIM / 32, H_DIM / 32), dim3(32, 8)>>>(w_rec, (__half*)p_wr);
    wtrans_kernel<<<dim3(H_DIM / 32, H_DIM / 32), dim3(32, 8)>>>(w_in, (__half*)p_wi);

    // xproj (tensor-core, 1-product fp16)
    xproj_mma_kernel<<<dim3(H_DIM / 64, (T_STEPS * B_DIM) / 128), 256, SMEM_XPROJ>>>(bias);

    // persistent scan: all 256 steps in one launch
    scan_kernel<<<dim3(H_DIM / 32, B_DIM / 64), 256, SMEM_SCAN>>>(out);
}